// round 10
// baseline (speedup 1.0000x reference)
#include <cuda_runtime.h>
#include <cuda_bf16.h>
#include <cuda_fp16.h>
#include <math.h>
#include <stdint.h>

// ---------------- problem constants ----------------
#define BB     2
#define SS     2048
#define NDIM   2048
#define NH     16
#define QRANK  1536
#define KVRANK 512
#define ROPE_D 64
#define NOPE_D 128
#define VDIM   128
#define QKH    192           // NOPE + ROPE
#define ROWS   (BB*SS)       // 4096
#define KVDIM  (NH*(NOPE_D+VDIM))  // 4096
#define QDIM   (NH*QKH)      // 3072
#define CDIM   (KVRANK+ROPE_D) // 576
#define ODIM   (NH*VDIM)     // 2048

typedef __half fp16;

// ---------------- scratch (device globals; no allocs allowed) ----------------
__device__ float g_cq [ROWS*QRANK];
__device__ float g_c  [ROWS*CDIM];
// fp16 operand planes
__device__ fp16 g_xf  [ROWS*NDIM];
__device__ fp16 g_wqaf[QRANK*NDIM];
__device__ fp16 g_wqbf[QDIM*QRANK];
__device__ fp16 g_wkvaf[CDIM*NDIM];
__device__ fp16 g_wkvbf[KVDIM*KVRANK];
__device__ fp16 g_wof [NDIM*ODIM];
__device__ fp16 g_cqf [ROWS*QRANK];
__device__ fp16 g_kvnf[ROWS*KVRANK];
__device__ fp16 g_af  [ROWS*ODIM];
// attention operands (head-major layouts)
__device__ fp16 g_qb [NH*ROWS*QKH];     // roped q
__device__ fp16 g_kb [NH*ROWS*QKH];     // k_nope | roped k_pe
__device__ fp16 g_vb [NH*ROWS*VDIM];    // v

// ---------------- helpers ----------------
__device__ __forceinline__ uint32_t packh2(float x, float y) {
    __half2 h = __floats2half2_rn(x, y);
    return *(uint32_t*)&h;
}

// fast exp2 on FMA pipe (x <= 0), rel err ~1e-6
__device__ __forceinline__ float fexp2(float x) {
    x = fmaxf(x, -126.f);
    float fl = floorf(x);
    float f = x - fl;
    float p = 1.535336188319500e-4f;
    p = fmaf(p, f, 1.339887440266574e-3f);
    p = fmaf(p, f, 9.618437357674640e-3f);
    p = fmaf(p, f, 5.550332471162809e-2f);
    p = fmaf(p, f, 2.402264791363012e-1f);
    p = fmaf(p, f, 6.931472028550421e-1f);
    p = fmaf(p, f, 1.0f);
    return p * __int_as_float(((int)fl + 127) << 23);
}

__global__ void cvt_fp16_k(const float4* __restrict__ in, uint2* __restrict__ out, int n4)
{
    int i = blockIdx.x * blockDim.x + threadIdx.x;
    if (i >= n4) return;
    float4 v = in[i];
    uint2 o;
    o.x = packh2(v.x, v.y);
    o.y = packh2(v.z, v.w);
    out[i] = o;
}

__device__ __forceinline__ uint32_t cvta_shared_u32(const void* p) {
    return (uint32_t)__cvta_generic_to_shared(p);
}

#define CP_ASYNC16(dst, src) \
    asm volatile("cp.async.cg.shared.global [%0], [%1], 16;" :: "r"(dst), "l"(src) : "memory")
#define CP_COMMIT() asm volatile("cp.async.commit_group;" ::: "memory")
#define CP_WAIT(N)  asm volatile("cp.async.wait_group %0;" :: "n"(N) : "memory")

#define LDSM_X4(r0,r1,r2,r3,addr) \
    asm volatile("ldmatrix.sync.aligned.m8n8.x4.shared.b16 {%0,%1,%2,%3}, [%4];" \
        : "=r"(r0), "=r"(r1), "=r"(r2), "=r"(r3) : "r"(addr))

#define LDSM_X4T(r0,r1,r2,r3,addr) \
    asm volatile("ldmatrix.sync.aligned.m8n8.x4.trans.shared.b16 {%0,%1,%2,%3}, [%4];" \
        : "=r"(r0), "=r"(r1), "=r"(r2), "=r"(r3) : "r"(addr))

#define MMA_F16(d, a, b) \
    asm volatile("mma.sync.aligned.m16n8k16.row.col.f32.f16.f16.f32 " \
        "{%0,%1,%2,%3}, {%4,%5,%6,%7}, {%8,%9}, {%0,%1,%2,%3};" \
        : "+f"((d)[0]), "+f"((d)[1]), "+f"((d)[2]), "+f"((d)[3]) \
        : "r"((a)[0]), "r"((a)[1]), "r"((a)[2]), "r"((a)[3]), "r"((b)[0]), "r"((b)[1]))

// fp16-accumulate variants (2 C regs = 4 halves)
#define MMA_F16H_ACC(d, a, b) \
    asm volatile("mma.sync.aligned.m16n8k16.row.col.f16.f16.f16.f16 " \
        "{%0,%1}, {%2,%3,%4,%5}, {%6,%7}, {%0,%1};" \
        : "+r"((d)[0]), "+r"((d)[1]) \
        : "r"((a)[0]), "r"((a)[1]), "r"((a)[2]), "r"((a)[3]), "r"((b)[0]), "r"((b)[1]))

#define MMA_F16H_Z(d, a, b, z) \
    asm volatile("mma.sync.aligned.m16n8k16.row.col.f16.f16.f16.f16 " \
        "{%0,%1}, {%2,%3,%4,%5}, {%6,%7}, {%8,%8};" \
        : "=r"((d)[0]), "=r"((d)[1]) \
        : "r"((a)[0]), "r"((a)[1]), "r"((a)[2]), "r"((a)[3]), "r"((b)[0]), "r"((b)[1]), \
          "r"(z))

// ---------------- fp16 GEMM: C[M,N] = A[M,K] * B[N,K]^T ----------------
// CTA 128 x NT, K-chunk 64 (=128B fp16 row), XOR-8 swizzle, cp.async ring.
// HACC=false: fp32-accum MMA, 3 stages, 2 CTAs/SM.
// HACC=true:  fp16-accum MMA within each 64-K chunk, promoted to fp32 per chunk;
//             4 stages, 1 CTA/SM (extra regs).
// MODE 0: write fp32 C. MODE 1: rope + fp16 head-major qb. MODE 2: fp16 kb/vb scatter.

template<int NT, int ST>
__device__ __forceinline__ void load_stage(
    const fp16* __restrict__ A, const fp16* __restrict__ B,
    int K, int m0, int n0, int k0, uint32_t sA, int tid)
{
    constexpr int TOT = (128 + NT) * 8;
    #pragma unroll
    for (int i = 0; i < TOT / 256; i++) {
        int c = tid + i * 256;
        int row = c >> 3;
        int u = c & 7;               // 16B unit within 128B row
        if (row < 128) {
            const fp16* src = A + (size_t)(m0 + row) * K + k0 + u * 8;
            uint32_t dst = sA + row * 128 + ((u ^ (row & 7)) << 4);
            CP_ASYNC16(dst, src);
        } else {
            int br = row - 128;
            const fp16* src = B + (size_t)(n0 + br) * K + k0 + u * 8;
            uint32_t dst = sA + 16384 + br * 128 + ((u ^ (br & 7)) << 4);
            CP_ASYNC16(dst, src);
        }
    }
}

template<int NT, int MODE, bool HACC>
__global__ __launch_bounds__(256, HACC ? 1 : 2) void gemm_fp16(
    const fp16* __restrict__ A, const fp16* __restrict__ B,
    float* __restrict__ C, fp16* __restrict__ O1, fp16* __restrict__ O2,
    const float* __restrict__ fc, int M, int N, int K)
{
    constexpr int WN = NT / 4;
    constexpr int NI = WN / 8;
    constexpr int CHUNK = 16384 + NT * 128;
    constexpr int ST = HACC ? 4 : 3;

    extern __shared__ char smem_raw[];
    const uint32_t sbase = cvta_shared_u32(smem_raw);

    const int tid = threadIdx.x;
    const int wid = tid >> 5, lane = tid & 31;
    const int wm = wid >> 2, wn = wid & 3;
    const int m0 = blockIdx.y * 128;
    const int n0 = blockIdx.x * NT;
    const int mat = lane >> 3, r8 = lane & 7;

    float acc[4][NI][4];
    #pragma unroll
    for (int i = 0; i < 4; i++)
        #pragma unroll
        for (int j = 0; j < NI; j++)
            #pragma unroll
            for (int e = 0; e < 4; e++) acc[i][j][e] = 0.f;

    const int kT = K / 64;
    const uint32_t zreg = 0u;

    #pragma unroll
    for (int st = 0; st < ST - 1; st++) {
        load_stage<NT, ST>(A, B, K, m0, n0, st * 64, sbase + st * CHUNK, tid);
        CP_COMMIT();
    }

    for (int it = 0; it < kT; it++) {
        CP_WAIT(ST - 2);
        __syncthreads();

        int nf = it + ST - 1;
        if (nf < kT)
            load_stage<NT, ST>(A, B, K, m0, n0, nf * 64,
                               sbase + (nf % ST) * CHUNK, tid);
        CP_COMMIT();

        const uint32_t sA = sbase + (it % ST) * CHUNK;
        const uint32_t sB = sA + 16384;

        uint32_t hacc[4][NI][2];   // used only when HACC

        #pragma unroll
        for (int s = 0; s < 4; s++) {          // four k16 steps per 64-chunk
            const int kg = s * 2 + (mat >> 1);
            uint32_t a[4][4];
            uint32_t b[NI][2];

            #pragma unroll
            for (int mt = 0; mt < 4; mt++) {
                int row = wm * 64 + mt * 16 + (mat & 1) * 8 + r8;
                uint32_t rb = sA + row * 128;
                int x7 = row & 7;
                LDSM_X4(a[mt][0], a[mt][1], a[mt][2], a[mt][3],
                        rb + ((kg ^ x7) << 4));
            }
            #pragma unroll
            for (int p = 0; p < NI / 2; p++) {
                int row = wn * WN + p * 16 + (mat & 1) * 8 + r8;
                uint32_t rb = sB + row * 128;
                int x7 = row & 7;
                uint32_t t0, t1, t2, t3;
                LDSM_X4(t0, t1, t2, t3, rb + ((kg ^ x7) << 4));
                b[2*p][0] = t0; b[2*p][1] = t2;
                b[2*p+1][0] = t1; b[2*p+1][1] = t3;
            }

            #pragma unroll
            for (int mt = 0; mt < 4; mt++)
                #pragma unroll
                for (int nt = 0; nt < NI; nt++) {
                    if (HACC) {
                        if (s == 0) MMA_F16H_Z(hacc[mt][nt], a[mt], b[nt], zreg);
                        else        MMA_F16H_ACC(hacc[mt][nt], a[mt], b[nt]);
                    } else {
                        MMA_F16(acc[mt][nt], a[mt], b[nt]);
                    }
                }
        }

        if (HACC) {
            // promote chunk fp16 accumulators into fp32 masters
            #pragma unroll
            for (int mt = 0; mt < 4; mt++)
                #pragma unroll
                for (int nt = 0; nt < NI; nt++) {
                    float2 f0 = __half22float2(*(__half2*)&hacc[mt][nt][0]);
                    float2 f1 = __half22float2(*(__half2*)&hacc[mt][nt][1]);
                    acc[mt][nt][0] += f0.x; acc[mt][nt][1] += f0.y;
                    acc[mt][nt][2] += f1.x; acc[mt][nt][3] += f1.y;
                }
        }
    }

    const int qm = lane >> 2, qn = (lane & 3) * 2;
    #pragma unroll
    for (int mt = 0; mt < 4; mt++)
        #pragma unroll
        for (int nt = 0; nt < NI; nt++) {
            int m = m0 + wm * 64 + mt * 16 + qm;     // rows m, m+8
            int n = n0 + wn * WN + nt * 8 + qn;      // cols n, n+1 (n even)
            float v0 = acc[mt][nt][0], v1 = acc[mt][nt][1];
            float v2 = acc[mt][nt][2], v3 = acc[mt][nt][3];
            if (MODE == 0) {
                *(float2*)&C[(size_t)m * N + n]       = make_float2(v0, v1);
                *(float2*)&C[(size_t)(m + 8) * N + n] = make_float2(v2, v3);
            } else if (MODE == 1) {
                // q: rope on pe pairs, fp16 head-major
                int h = n / QKH, p2 = n % QKH;
                if (p2 >= NOPE_D) {
                    int pp = (p2 - NOPE_D) >> 1;
                    int s0 = m & (SS - 1), s8 = (m + 8) & (SS - 1);
                    float cs0 = fc[(s0 * 32 + pp) * 2], sn0 = fc[(s0 * 32 + pp) * 2 + 1];
                    float cs8 = fc[(s8 * 32 + pp) * 2], sn8 = fc[(s8 * 32 + pp) * 2 + 1];
                    float r0 = v0 * cs0 - v1 * sn0, i0 = v0 * sn0 + v1 * cs0;
                    float r2 = v2 * cs8 - v3 * sn8, i2 = v2 * sn8 + v3 * cs8;
                    v0 = r0; v1 = i0; v2 = r2; v3 = i2;
                }
                fp16* dst = O1 + ((size_t)h * ROWS + m) * QKH + p2;
                *(uint32_t*)dst               = packh2(v0, v1);
                *(uint32_t*)(dst + 8 * QKH)   = packh2(v2, v3);
            } else {
                // kv: scatter k_nope -> O1 (kb), v -> O2 (vb)
                int h = n >> 8, c2 = n & 255;
                if (c2 < NOPE_D) {
                    fp16* dst = O1 + ((size_t)h * ROWS + m) * QKH + c2;
                    *(uint32_t*)dst             = packh2(v0, v1);
                    *(uint32_t*)(dst + 8 * QKH) = packh2(v2, v3);
                } else {
                    fp16* dst = O2 + ((size_t)h * ROWS + m) * VDIM + (c2 - NOPE_D);
                    *(uint32_t*)dst              = packh2(v0, v1);
                    *(uint32_t*)(dst + 8 * VDIM) = packh2(v2, v3);
                }
            }
        }
}

// ---------------- RMSNorm -> fp16 plane ----------------
__global__ __launch_bounds__(256) void rmsnorm_cvt_k(
    const float* __restrict__ in, fp16* __restrict__ o,
    const float* __restrict__ w, int L, int sin)
{
    __shared__ float red[8];
    const int row = blockIdx.x;
    const float* ip = in + (size_t)row * sin;
    float ss = 0.f;
    for (int i = threadIdx.x; i < L; i += 256) {
        float v = ip[i];
        ss = fmaf(v, v, ss);
    }
    #pragma unroll
    for (int off = 16; off; off >>= 1)
        ss += __shfl_xor_sync(0xffffffffu, ss, off);
    if ((threadIdx.x & 31) == 0) red[threadIdx.x >> 5] = ss;
    __syncthreads();
    if (threadIdx.x == 0) {
        float tot = 0.f;
        #pragma unroll
        for (int i = 0; i < 8; i++) tot += red[i];
        red[0] = rsqrtf(tot / (float)L + 1e-6f);
    }
    __syncthreads();
    float inv = red[0];
    for (int i = threadIdx.x; i < L; i += 256)
        o[(size_t)row * L + i] = __float2half_rn(ip[i] * inv * w[i]);
}

// ---------------- k_pe conversion (rope; shared across heads) ----------------
__global__ void kpe_conv_k(const float* __restrict__ c, const float* __restrict__ fc,
                           fp16* __restrict__ kb)
{
    int idx = blockIdx.x * blockDim.x + threadIdx.x;
    if (idx >= NH * ROWS * 32) return;
    int p = idx & 31;
    int rowh = idx >> 5;
    int row = rowh & (ROWS - 1);
    int h = rowh >> 12;
    int s = row & (SS - 1);
    const float* src = c + (size_t)row * CDIM + KVRANK + 2 * p;
    float a = src[0], b = src[1];
    float cs = fc[(s * 32 + p) * 2 + 0];
    float sn = fc[(s * 32 + p) * 2 + 1];
    float v0 = a * cs - b * sn;
    float v1 = a * sn + b * cs;
    *(uint32_t*)(kb + ((size_t)h * ROWS + row) * QKH + NOPE_D + 2 * p) = packh2(v0, v1);
}

// ---------------- tensor-core flash attention (fp16) ----------------
// q-tile 128 rows, 8 warps x m16; key tiles 64; D=192.
// smem (fp16 elems): Q 128x200, K[2] 64x200, V[2] 64x136.
#define ATT_SMEM_BYTES ((128*200 + 2*64*200 + 2*64*136) * 2)

__global__ __launch_bounds__(256, 1) void attn_mma(
    const fp16* __restrict__ gq, const fp16* __restrict__ gk,
    const fp16* __restrict__ gv, fp16* __restrict__ go)
{
    extern __shared__ fp16 asm_[];
    const uint32_t sQ = cvta_shared_u32(asm_);
    const uint32_t sK = sQ + 128 * 200 * 2;
    const uint32_t sV = sK + 2 * 64 * 200 * 2;

    const int tid = threadIdx.x;
    const int wid = tid >> 5, lane = tid & 31;
    const int qt = gridDim.x - 1 - blockIdx.x;
    const int q0 = qt * 128;
    const int h  = blockIdx.y;
    const int b  = blockIdx.z;
    const size_t hb = (size_t)h * ROWS + b * SS;

    {
        const fp16* qbase = gq + (hb + q0) * QKH;
        for (int i = tid; i < 3072; i += 256) {
            int row = i / 24, u = i - row * 24;
            CP_ASYNC16(sQ + (row * 200 + u * 8) * 2, qbase + row * QKH + u * 8);
        }
    }

    const int nT = q0 / 64 + 2;

    auto load_tile = [&](int n0, int buf) {
        const fp16* kbase = gk + (hb + n0) * QKH;
        uint32_t kd = sK + buf * (64 * 200 * 2);
        for (int i = tid; i < 1536; i += 256) {
            int row = i / 24, u = i - row * 24;
            CP_ASYNC16(kd + (row * 200 + u * 8) * 2, kbase + row * QKH + u * 8);
        }
        const fp16* vbase = gv + (hb + n0) * VDIM;
        uint32_t vd = sV + buf * (64 * 136 * 2);
        for (int i = tid; i < 1024; i += 256) {
            int row = i >> 4, u = i & 15;
            CP_ASYNC16(vd + (row * 136 + u * 8) * 2, vbase + row * VDIM + u * 8);
        }
    };

    load_tile(0, 0);
    CP_COMMIT();

    float out[16][4];
    #pragma unroll
    for (int f = 0; f < 16; f++)
        #pragma unroll
        for (int e = 0; e < 4; e++) out[f][e] = 0.f;
    float m0 = -1e30f, m1 = -1e30f, l0 = 0.f, l1 = 0.f;

    const int mat = lane >> 3, r8 = lane & 7;
    const uint32_t aQ = sQ + ((wid * 16 + (lane & 15)) * 200 + (lane >> 4) * 8) * 2;
    const float sc2 = 0.07216878364870323f * 1.4426950408889634f;
    const int growA = q0 + wid * 16 + (lane >> 2);

    for (int t = 0; t < nT; t++) {
        const int buf = t & 1;
        if (t + 1 < nT) load_tile(64 * (t + 1), buf ^ 1);
        CP_COMMIT();
        CP_WAIT(1);
        __syncthreads();

        const int n0 = 64 * t;
        const bool active = (n0 <= q0 + wid * 16 + 15);
        if (active) {
            // ---- S = Q @ K^T ----
            float s[8][4];
            #pragma unroll
            for (int f = 0; f < 8; f++)
                #pragma unroll
                for (int e = 0; e < 4; e++) s[f][e] = 0.f;

            const uint32_t kB = sK + buf * (64 * 200 * 2)
                              + (((mat >> 1) * 8 + r8) * 200 + (mat & 1) * 8) * 2;
            #pragma unroll
            for (int kt = 0; kt < 12; kt++) {
                uint32_t a[4];
                LDSM_X4(a[0], a[1], a[2], a[3], aQ + kt * 32);
                #pragma unroll
                for (int g = 0; g < 4; g++) {
                    uint32_t b0, b1, b2, b3;
                    LDSM_X4(b0, b1, b2, b3, kB + (g * 16 * 200) * 2 + kt * 32);
                    uint32_t bb0[2] = {b0, b1}, bb1[2] = {b2, b3};
                    MMA_F16(s[2*g],   a, bb0);
                    MMA_F16(s[2*g+1], a, bb1);
                }
            }

            // ---- online softmax (log2 domain) ----
            const bool needmask = (n0 + 63 > q0 + wid * 16);
            const int colb = n0 + 2 * (lane & 3);
            float rm0 = -1e30f, rm1 = -1e30f;
            #pragma unroll
            for (int f = 0; f < 8; f++) {
                #pragma unroll
                for (int j = 0; j < 2; j++) {
                    int col = colb + f * 8 + j;
                    float z0 = s[f][j]     * sc2;
                    float z1 = s[f][2 + j] * sc2;
                    if (needmask) {
                        if (col > growA)     z0 = -1e30f;
                        if (col > growA + 8) z1 = -1e30f;
                    }
                    s[f][j] = z0; s[f][2 + j] = z1;
                    rm0 = fmaxf(rm0, z0); rm1 = fmaxf(rm1, z1);
                }
            }
            rm0 = fmaxf(rm0, __shfl_xor_sync(0xffffffffu, rm0, 1));
            rm0 = fmaxf(rm0, __shfl_xor_sync(0xffffffffu, rm0, 2));
            rm1 = fmaxf(rm1, __shfl_xor_sync(0xffffffffu, rm1, 1));
            rm1 = fmaxf(rm1, __shfl_xor_sync(0xffffffffu, rm1, 2));
            float mn0 = fmaxf(m0, rm0), mn1 = fmaxf(m1, rm1);
            float al0 = fexp2(m0 - mn0), al1 = fexp2(m1 - mn1);
            m0 = mn0; m1 = mn1;

            float rs0 = 0.f, rs1 = 0.f;
            #pragma unroll
            for (int f = 0; f < 8; f++) {
                #pragma unroll
                for (int j = 0; j < 2; j++) {
                    float p0 = fexp2(s[f][j]     - mn0);
                    float p1 = fexp2(s[f][2 + j] - mn1);
                    s[f][j] = p0; s[f][2 + j] = p1;
                    rs0 += p0; rs1 += p1;
                }
            }
            rs0 += __shfl_xor_sync(0xffffffffu, rs0, 1);
            rs0 += __shfl_xor_sync(0xffffffffu, rs0, 2);
            rs1 += __shfl_xor_sync(0xffffffffu, rs1, 1);
            rs1 += __shfl_xor_sync(0xffffffffu, rs1, 2);
            l0 = l0 * al0 + rs0;
            l1 = l1 * al1 + rs1;

            #pragma unroll
            for (int f = 0; f < 16; f++) {
                out[f][0] *= al0; out[f][1] *= al0;
                out[f][2] *= al1; out[f][3] *= al1;
            }

            // ---- O += P @ V (fp16) ----
            const uint32_t vB = sV + buf * (64 * 136 * 2)
                              + (((mat & 1) * 8 + r8) * 136 + (mat >> 1) * 8) * 2;
            #pragma unroll
            for (int kt = 0; kt < 4; kt++) {
                uint32_t pa[4];
                pa[0] = packh2(s[2*kt][0],   s[2*kt][1]);
                pa[1] = packh2(s[2*kt][2],   s[2*kt][3]);
                pa[2] = packh2(s[2*kt+1][0], s[2*kt+1][1]);
                pa[3] = packh2(s[2*kt+1][2], s[2*kt+1][3]);
                const uint32_t rowOff = (kt * 16 * 136) * 2;
                #pragma unroll
                for (int gv = 0; gv < 8; gv++) {
                    uint32_t h0, h1, h2, h3;
                    LDSM_X4T(h0, h1, h2, h3, vB + rowOff + gv * 32);
                    uint32_t bh0[2] = {h0, h1}, bh1[2] = {h2, h3};
                    MMA_F16(out[2*gv],   pa, bh0);
                    MMA_F16(out[2*gv+1], pa, bh1);
                }
            }
        }
        __syncthreads();
    }

    // ---- finalize ----
    float inv0 = 1.f / l0, inv1 = 1.f / l1;
    size_t r0g = (size_t)(b * SS + q0 + wid * 16 + (lane >> 2));
    size_t base0 = r0g * ODIM + h * VDIM + 2 * (lane & 3);
    size_t base1 = base0 + 8 * (size_t)ODIM;
    #pragma unroll
    for (int f = 0; f < 16; f++) {
        *(uint32_t*)&go[base0 + f * 8] = packh2(out[f][0] * inv0, out[f][1] * inv0);
        *(uint32_t*)&go[base1 + f * 8] = packh2(out[f][2] * inv1, out[f][3] * inv1);
    }
}

// ---------------- launcher ----------------
static inline void cvt_pass_s(const float* src, fp16* dst, size_t n, cudaStream_t st)
{
    int n4 = (int)(n / 4);
    cvt_fp16_k<<<(n4 + 255) / 256, 256, 0, st>>>((const float4*)src, (uint2*)dst, n4);
}

extern "C" void kernel_launch(void* const* d_in, const int* in_sizes, int n_in,
                              void* d_out, int out_size)
{
    const float* x     = (const float*)d_in[0];
    const float* fc    = (const float*)d_in[1];
    const float* wq_a  = (const float*)d_in[2];
    const float* qnw   = (const float*)d_in[3];
    const float* wq_b  = (const float*)d_in[4];
    const float* wkv_a = (const float*)d_in[5];
    const float* kvnw  = (const float*)d_in[6];
    const float* wkv_b = (const float*)d_in[7];
    const float* wo    = (const float*)d_in[8];
    float* out = (float*)d_out;

    float *cq, *c;
    fp16 *xf, *wqaf, *wqbf, *wkvaf, *wkvbf, *wof, *cqf, *kvnf, *af, *qb, *kb, *vb;
    cudaGetSymbolAddress((void**)&cq,   g_cq);
    cudaGetSymbolAddress((void**)&c,    g_c);
    cudaGetSymbolAddress((void**)&xf,   g_xf);
    cudaGetSymbolAddress((void**)&wqaf, g_wqaf);
    cudaGetSymbolAddress((void**)&wqbf, g_wqbf);
    cudaGetSymbolAddress((void**)&wkvaf,g_wkvaf);
    cudaGetSymbolAddress((void**)&wkvbf,g_wkvbf);
    cudaGetSymbolAddress((void**)&wof,  g_wof);
    cudaGetSymbolAddress((void**)&cqf,  g_cqf);
    cudaGetSymbolAddress((void**)&kvnf, g_kvnf);
    cudaGetSymbolAddress((void**)&af,   g_af);
    cudaGetSymbolAddress((void**)&qb,   g_qb);
    cudaGetSymbolAddress((void**)&kb,   g_kb);
    cudaGetSymbolAddress((void**)&vb,   g_vb);

    static cudaStream_t s1 = nullptr;
    static cudaEvent_t eFork = nullptr, eJoin = nullptr;
    if (s1 == nullptr) {
        cudaStreamCreateWithFlags(&s1, cudaStreamNonBlocking);
        cudaEventCreateWithFlags(&eFork, cudaEventDisableTiming);
        cudaEventCreateWithFlags(&eJoin, cudaEventDisableTiming);
    }
    cudaStream_t s0 = 0;

    const int smemH   = 4 * (16384 + 128*128); // 131072 (HACC, 4 stages)
    const int smem64  = 3 * (16384 + 64*128);  // 73728
    cudaFuncSetAttribute(gemm_fp16<128,0,true>,  cudaFuncAttributeMaxDynamicSharedMemorySize, smemH);
    cudaFuncSetAttribute(gemm_fp16<128,1,true>,  cudaFuncAttributeMaxDynamicSharedMemorySize, smemH);
    cudaFuncSetAttribute(gemm_fp16<128,2,true>,  cudaFuncAttributeMaxDynamicSharedMemorySize, smemH);
    cudaFuncSetAttribute(gemm_fp16<64,0,false>,  cudaFuncAttributeMaxDynamicSharedMemorySize, smem64);
    cudaFuncSetAttribute(attn_mma, cudaFuncAttributeMaxDynamicSharedMemorySize, ATT_SMEM_BYTES);

    // ---- s0: x + q-branch weights; fork point after xf ----
    cvt_pass_s(x,    xf,   (size_t)ROWS * NDIM, s0);
    cudaEventRecord(eFork, s0);
    cvt_pass_s(wq_a, wqaf, (size_t)QRANK * NDIM, s0);
    cvt_pass_s(wq_b, wqbf, (size_t)QDIM * QRANK, s0);
    cvt_pass_s(wo,   wof,  (size_t)NDIM * ODIM, s0);

    // ---- s1 (kv branch) ----
    cudaStreamWaitEvent(s1, eFork, 0);
    cvt_pass_s(wkv_a, wkvaf, (size_t)CDIM * NDIM, s1);
    cvt_pass_s(wkv_b, wkvbf, (size_t)KVDIM * KVRANK, s1);
    gemm_fp16<64,0,false><<<dim3(CDIM/64, ROWS/128), 256, smem64, s1>>>(
        xf, wkvaf, c, nullptr, nullptr, nullptr, ROWS, CDIM, NDIM);
    rmsnorm_cvt_k<<<ROWS, 256, 0, s1>>>(c, kvnf, kvnw, KVRANK, CDIM);
    kpe_conv_k<<<(NH*ROWS*32 + 255)/256, 256, 0, s1>>>(c, fc, kb);
    gemm_fp16<128,2,true><<<dim3(KVDIM/128, ROWS/128), 256, smemH, s1>>>(
        kvnf, wkvbf, nullptr, kb, vb, nullptr, ROWS, KVDIM, KVRANK);
    cudaEventRecord(eJoin, s1);

    // ---- s0 (q branch) ----
    gemm_fp16<128,0,true><<<dim3(QRANK/128, ROWS/128), 256, smemH, s0>>>(
        xf, wqaf, cq, nullptr, nullptr, nullptr, ROWS, QRANK, NDIM);
    rmsnorm_cvt_k<<<ROWS, 256, 0, s0>>>(cq, cqf, qnw, QRANK, QRANK);
    gemm_fp16<128,1,true><<<dim3(QDIM/128, ROWS/128), 256, smemH, s0>>>(
        cqf, wqbf, nullptr, qb, nullptr, fc, ROWS, QDIM, QRANK);

    // ---- join, attention, output GEMM ----
    cudaStreamWaitEvent(s0, eJoin, 0);
    attn_mma<<<dim3(SS/128, NH, BB), 256, ATT_SMEM_BYTES, s0>>>(qb, kb, vb, af);
    gemm_fp16<128,0,true><<<dim3(NDIM/128, ROWS/128), 256, smemH, s0>>>(
        af, wof, out, nullptr, nullptr, nullptr, ROWS, NDIM, ODIM);
}

// round 11
// speedup vs baseline: 1.1453x; 1.1453x over previous
#include <cuda_runtime.h>
#include <cuda_bf16.h>
#include <cuda_fp16.h>
#include <math.h>
#include <stdint.h>

// ---------------- problem constants ----------------
#define BB     2
#define SS     2048
#define NDIM   2048
#define NH     16
#define QRANK  1536
#define KVRANK 512
#define ROPE_D 64
#define NOPE_D 128
#define VDIM   128
#define QKH    192           // NOPE + ROPE
#define ROWS   (BB*SS)       // 4096
#define KVDIM  (NH*(NOPE_D+VDIM))  // 4096
#define QDIM   (NH*QKH)      // 3072
#define CDIM   (KVRANK+ROPE_D) // 576
#define ODIM   (NH*VDIM)     // 2048

typedef __half fp16;

// ---------------- scratch (device globals; no allocs allowed) ----------------
__device__ float g_cq [ROWS*QRANK];
__device__ float g_c  [ROWS*CDIM];
// fp16 operand planes
__device__ fp16 g_xf  [ROWS*NDIM];
__device__ fp16 g_wqaf[QRANK*NDIM];
__device__ fp16 g_wqbf[QDIM*QRANK];
__device__ fp16 g_wkvaf[CDIM*NDIM];
__device__ fp16 g_wkvbf[KVDIM*KVRANK];
__device__ fp16 g_wof [NDIM*ODIM];
__device__ fp16 g_cqf [ROWS*QRANK];
__device__ fp16 g_kvnf[ROWS*KVRANK];
__device__ fp16 g_af  [ROWS*ODIM];
// attention operands (head-major layouts)
__device__ fp16 g_qb [NH*ROWS*QKH];     // roped q
__device__ fp16 g_kb [NH*ROWS*QKH];     // k_nope | roped k_pe
__device__ fp16 g_vb [NH*ROWS*VDIM];    // v

// ---------------- helpers ----------------
__device__ __forceinline__ uint32_t packh2(float x, float y) {
    __half2 h = __floats2half2_rn(x, y);
    return *(uint32_t*)&h;
}

// fast exp2 on FMA pipe (x <= 0), rel err ~1e-6
__device__ __forceinline__ float fexp2(float x) {
    x = fmaxf(x, -126.f);
    float fl = floorf(x);
    float f = x - fl;
    float p = 1.535336188319500e-4f;
    p = fmaf(p, f, 1.339887440266574e-3f);
    p = fmaf(p, f, 9.618437357674640e-3f);
    p = fmaf(p, f, 5.550332471162809e-2f);
    p = fmaf(p, f, 2.402264791363012e-1f);
    p = fmaf(p, f, 6.931472028550421e-1f);
    p = fmaf(p, f, 1.0f);
    return p * __int_as_float(((int)fl + 127) << 23);
}

__global__ void cvt_fp16_k(const float4* __restrict__ in, uint2* __restrict__ out, int n4)
{
    int i = blockIdx.x * blockDim.x + threadIdx.x;
    if (i >= n4) return;
    float4 v = in[i];
    uint2 o;
    o.x = packh2(v.x, v.y);
    o.y = packh2(v.z, v.w);
    out[i] = o;
}

__device__ __forceinline__ uint32_t cvta_shared_u32(const void* p) {
    return (uint32_t)__cvta_generic_to_shared(p);
}

#define CP_ASYNC16(dst, src) \
    asm volatile("cp.async.cg.shared.global [%0], [%1], 16;" :: "r"(dst), "l"(src) : "memory")
#define CP_COMMIT() asm volatile("cp.async.commit_group;" ::: "memory")
#define CP_WAIT(N)  asm volatile("cp.async.wait_group %0;" :: "n"(N) : "memory")

#define LDSM_X4(r0,r1,r2,r3,addr) \
    asm volatile("ldmatrix.sync.aligned.m8n8.x4.shared.b16 {%0,%1,%2,%3}, [%4];" \
        : "=r"(r0), "=r"(r1), "=r"(r2), "=r"(r3) : "r"(addr))

#define LDSM_X4T(r0,r1,r2,r3,addr) \
    asm volatile("ldmatrix.sync.aligned.m8n8.x4.trans.shared.b16 {%0,%1,%2,%3}, [%4];" \
        : "=r"(r0), "=r"(r1), "=r"(r2), "=r"(r3) : "r"(addr))

#define MMA_F16(d, a, b) \
    asm volatile("mma.sync.aligned.m16n8k16.row.col.f32.f16.f16.f32 " \
        "{%0,%1,%2,%3}, {%4,%5,%6,%7}, {%8,%9}, {%0,%1,%2,%3};" \
        : "+f"((d)[0]), "+f"((d)[1]), "+f"((d)[2]), "+f"((d)[3]) \
        : "r"((a)[0]), "r"((a)[1]), "r"((a)[2]), "r"((a)[3]), "r"((b)[0]), "r"((b)[1]))

// ---------------- fp16 GEMM: C[M,N] = A[M,K] * B[N,K]^T (fp32 accum) ----------------
// CTA 128 x NT, K-chunk 64 (=128B fp16 row), XOR-8 swizzle, 3-stage cp.async ring,
// 2 CTAs/SM. 8 warps: 2(M) x 4(N), warp tile 64 x NT/4.
// MODE 0: write fp32 C. MODE 1: rope + fp16 head-major qb. MODE 2: fp16 kb/vb scatter.
#define STAGES 3

template<int NT>
__device__ __forceinline__ void load_stage(
    const fp16* __restrict__ A, const fp16* __restrict__ B,
    int K, int m0, int n0, int k0, uint32_t sA, int tid)
{
    constexpr int TOT = (128 + NT) * 8;
    #pragma unroll
    for (int i = 0; i < TOT / 256; i++) {
        int c = tid + i * 256;
        int row = c >> 3;
        int u = c & 7;               // 16B unit within 128B row
        if (row < 128) {
            const fp16* src = A + (size_t)(m0 + row) * K + k0 + u * 8;
            uint32_t dst = sA + row * 128 + ((u ^ (row & 7)) << 4);
            CP_ASYNC16(dst, src);
        } else {
            int br = row - 128;
            const fp16* src = B + (size_t)(n0 + br) * K + k0 + u * 8;
            uint32_t dst = sA + 16384 + br * 128 + ((u ^ (br & 7)) << 4);
            CP_ASYNC16(dst, src);
        }
    }
}

template<int NT, int MODE>
__global__ __launch_bounds__(256, 2) void gemm_fp16(
    const fp16* __restrict__ A, const fp16* __restrict__ B,
    float* __restrict__ C, fp16* __restrict__ O1, fp16* __restrict__ O2,
    const float* __restrict__ fc, int M, int N, int K)
{
    constexpr int WN = NT / 4;
    constexpr int NI = WN / 8;
    constexpr int CHUNK = 16384 + NT * 128;

    extern __shared__ char smem_raw[];
    const uint32_t sbase = cvta_shared_u32(smem_raw);

    const int tid = threadIdx.x;
    const int wid = tid >> 5, lane = tid & 31;
    const int wm = wid >> 2, wn = wid & 3;
    const int m0 = blockIdx.y * 128;
    const int n0 = blockIdx.x * NT;
    const int mat = lane >> 3, r8 = lane & 7;

    float acc[4][NI][4];
    #pragma unroll
    for (int i = 0; i < 4; i++)
        #pragma unroll
        for (int j = 0; j < NI; j++)
            #pragma unroll
            for (int e = 0; e < 4; e++) acc[i][j][e] = 0.f;

    const int kT = K / 64;

    #pragma unroll
    for (int st = 0; st < STAGES - 1; st++) {
        load_stage<NT>(A, B, K, m0, n0, st * 64, sbase + st * CHUNK, tid);
        CP_COMMIT();
    }

    for (int it = 0; it < kT; it++) {
        CP_WAIT(STAGES - 2);
        __syncthreads();

        int nf = it + STAGES - 1;
        if (nf < kT)
            load_stage<NT>(A, B, K, m0, n0, nf * 64,
                           sbase + (nf % STAGES) * CHUNK, tid);
        CP_COMMIT();

        const uint32_t sA = sbase + (it % STAGES) * CHUNK;
        const uint32_t sB = sA + 16384;

        #pragma unroll
        for (int s = 0; s < 4; s++) {          // four k16 steps per 64-chunk
            const int kg = s * 2 + (mat >> 1);
            uint32_t a[4][4];
            uint32_t b[NI][2];

            #pragma unroll
            for (int mt = 0; mt < 4; mt++) {
                int row = wm * 64 + mt * 16 + (mat & 1) * 8 + r8;
                uint32_t rb = sA + row * 128;
                int x7 = row & 7;
                LDSM_X4(a[mt][0], a[mt][1], a[mt][2], a[mt][3],
                        rb + ((kg ^ x7) << 4));
            }
            #pragma unroll
            for (int p = 0; p < NI / 2; p++) {
                int row = wn * WN + p * 16 + (mat & 1) * 8 + r8;
                uint32_t rb = sB + row * 128;
                int x7 = row & 7;
                uint32_t t0, t1, t2, t3;
                LDSM_X4(t0, t1, t2, t3, rb + ((kg ^ x7) << 4));
                b[2*p][0] = t0; b[2*p][1] = t2;
                b[2*p+1][0] = t1; b[2*p+1][1] = t3;
            }

            #pragma unroll
            for (int mt = 0; mt < 4; mt++)
                #pragma unroll
                for (int nt = 0; nt < NI; nt++)
                    MMA_F16(acc[mt][nt], a[mt], b[nt]);
        }
    }

    const int qm = lane >> 2, qn = (lane & 3) * 2;
    #pragma unroll
    for (int mt = 0; mt < 4; mt++)
        #pragma unroll
        for (int nt = 0; nt < NI; nt++) {
            int m = m0 + wm * 64 + mt * 16 + qm;     // rows m, m+8
            int n = n0 + wn * WN + nt * 8 + qn;      // cols n, n+1 (n even)
            float v0 = acc[mt][nt][0], v1 = acc[mt][nt][1];
            float v2 = acc[mt][nt][2], v3 = acc[mt][nt][3];
            if (MODE == 0) {
                *(float2*)&C[(size_t)m * N + n]       = make_float2(v0, v1);
                *(float2*)&C[(size_t)(m + 8) * N + n] = make_float2(v2, v3);
            } else if (MODE == 1) {
                // q: rope on pe pairs, fp16 head-major
                int h = n / QKH, p2 = n % QKH;
                if (p2 >= NOPE_D) {
                    int pp = (p2 - NOPE_D) >> 1;
                    int s0 = m & (SS - 1), s8 = (m + 8) & (SS - 1);
                    float cs0 = fc[(s0 * 32 + pp) * 2], sn0 = fc[(s0 * 32 + pp) * 2 + 1];
                    float cs8 = fc[(s8 * 32 + pp) * 2], sn8 = fc[(s8 * 32 + pp) * 2 + 1];
                    float r0 = v0 * cs0 - v1 * sn0, i0 = v0 * sn0 + v1 * cs0;
                    float r2 = v2 * cs8 - v3 * sn8, i2 = v2 * sn8 + v3 * cs8;
                    v0 = r0; v1 = i0; v2 = r2; v3 = i2;
                }
                fp16* dst = O1 + ((size_t)h * ROWS + m) * QKH + p2;
                *(uint32_t*)dst               = packh2(v0, v1);
                *(uint32_t*)(dst + 8 * QKH)   = packh2(v2, v3);
            } else {
                // kv: scatter k_nope -> O1 (kb), v -> O2 (vb)
                int h = n >> 8, c2 = n & 255;
                if (c2 < NOPE_D) {
                    fp16* dst = O1 + ((size_t)h * ROWS + m) * QKH + c2;
                    *(uint32_t*)dst             = packh2(v0, v1);
                    *(uint32_t*)(dst + 8 * QKH) = packh2(v2, v3);
                } else {
                    fp16* dst = O2 + ((size_t)h * ROWS + m) * VDIM + (c2 - NOPE_D);
                    *(uint32_t*)dst              = packh2(v0, v1);
                    *(uint32_t*)(dst + 8 * VDIM) = packh2(v2, v3);
                }
            }
        }
}

// ---------------- RMSNorm -> fp16 plane ----------------
__global__ __launch_bounds__(256) void rmsnorm_cvt_k(
    const float* __restrict__ in, fp16* __restrict__ o,
    const float* __restrict__ w, int L, int sin)
{
    __shared__ float red[8];
    const int row = blockIdx.x;
    const float* ip = in + (size_t)row * sin;
    float ss = 0.f;
    for (int i = threadIdx.x; i < L; i += 256) {
        float v = ip[i];
        ss = fmaf(v, v, ss);
    }
    #pragma unroll
    for (int off = 16; off; off >>= 1)
        ss += __shfl_xor_sync(0xffffffffu, ss, off);
    if ((threadIdx.x & 31) == 0) red[threadIdx.x >> 5] = ss;
    __syncthreads();
    if (threadIdx.x == 0) {
        float tot = 0.f;
        #pragma unroll
        for (int i = 0; i < 8; i++) tot += red[i];
        red[0] = rsqrtf(tot / (float)L + 1e-6f);
    }
    __syncthreads();
    float inv = red[0];
    for (int i = threadIdx.x; i < L; i += 256)
        o[(size_t)row * L + i] = __float2half_rn(ip[i] * inv * w[i]);
}

// ---------------- k_pe conversion (rope; shared across heads) ----------------
__global__ void kpe_conv_k(const float* __restrict__ c, const float* __restrict__ fc,
                           fp16* __restrict__ kb)
{
    int idx = blockIdx.x * blockDim.x + threadIdx.x;
    if (idx >= NH * ROWS * 32) return;
    int p = idx & 31;
    int rowh = idx >> 5;
    int row = rowh & (ROWS - 1);
    int h = rowh >> 12;
    int s = row & (SS - 1);
    const float* src = c + (size_t)row * CDIM + KVRANK + 2 * p;
    float a = src[0], b = src[1];
    float cs = fc[(s * 32 + p) * 2 + 0];
    float sn = fc[(s * 32 + p) * 2 + 1];
    float v0 = a * cs - b * sn;
    float v1 = a * sn + b * cs;
    *(uint32_t*)(kb + ((size_t)h * ROWS + row) * QKH + NOPE_D + 2 * p) = packh2(v0, v1);
}

// ---------------- tensor-core flash attention (fp16) ----------------
// q-tile 128 rows, 8 warps x m16; key tiles 64; D=192.
// smem (fp16 elems): Q 128x200, K[2] 64x200, V[2] 64x136.
#define ATT_SMEM_BYTES ((128*200 + 2*64*200 + 2*64*136) * 2)

__global__ __launch_bounds__(256, 1) void attn_mma(
    const fp16* __restrict__ gq, const fp16* __restrict__ gk,
    const fp16* __restrict__ gv, fp16* __restrict__ go)
{
    extern __shared__ fp16 asm_[];
    const uint32_t sQ = cvta_shared_u32(asm_);
    const uint32_t sK = sQ + 128 * 200 * 2;
    const uint32_t sV = sK + 2 * 64 * 200 * 2;

    const int tid = threadIdx.x;
    const int wid = tid >> 5, lane = tid & 31;
    const int qt = gridDim.x - 1 - blockIdx.x;
    const int q0 = qt * 128;
    const int h  = blockIdx.y;
    const int b  = blockIdx.z;
    const size_t hb = (size_t)h * ROWS + b * SS;

    {
        const fp16* qbase = gq + (hb + q0) * QKH;
        for (int i = tid; i < 3072; i += 256) {
            int row = i / 24, u = i - row * 24;
            CP_ASYNC16(sQ + (row * 200 + u * 8) * 2, qbase + row * QKH + u * 8);
        }
    }

    const int nT = q0 / 64 + 2;

    auto load_tile = [&](int n0, int buf) {
        const fp16* kbase = gk + (hb + n0) * QKH;
        uint32_t kd = sK + buf * (64 * 200 * 2);
        for (int i = tid; i < 1536; i += 256) {
            int row = i / 24, u = i - row * 24;
            CP_ASYNC16(kd + (row * 200 + u * 8) * 2, kbase + row * QKH + u * 8);
        }
        const fp16* vbase = gv + (hb + n0) * VDIM;
        uint32_t vd = sV + buf * (64 * 136 * 2);
        for (int i = tid; i < 1024; i += 256) {
            int row = i >> 4, u = i & 15;
            CP_ASYNC16(vd + (row * 136 + u * 8) * 2, vbase + row * VDIM + u * 8);
        }
    };

    load_tile(0, 0);
    CP_COMMIT();

    float out[16][4];
    #pragma unroll
    for (int f = 0; f < 16; f++)
        #pragma unroll
        for (int e = 0; e < 4; e++) out[f][e] = 0.f;
    float m0 = -1e30f, m1 = -1e30f, l0 = 0.f, l1 = 0.f;

    const int mat = lane >> 3, r8 = lane & 7;
    const uint32_t aQ = sQ + ((wid * 16 + (lane & 15)) * 200 + (lane >> 4) * 8) * 2;
    const float sc2 = 0.07216878364870323f * 1.4426950408889634f;
    const int growA = q0 + wid * 16 + (lane >> 2);

    for (int t = 0; t < nT; t++) {
        const int buf = t & 1;
        if (t + 1 < nT) load_tile(64 * (t + 1), buf ^ 1);
        CP_COMMIT();
        CP_WAIT(1);
        __syncthreads();

        const int n0 = 64 * t;
        const bool active = (n0 <= q0 + wid * 16 + 15);
        if (active) {
            // ---- S = Q @ K^T ----
            float s[8][4];
            #pragma unroll
            for (int f = 0; f < 8; f++)
                #pragma unroll
                for (int e = 0; e < 4; e++) s[f][e] = 0.f;

            const uint32_t kB = sK + buf * (64 * 200 * 2)
                              + (((mat >> 1) * 8 + r8) * 200 + (mat & 1) * 8) * 2;
            #pragma unroll
            for (int kt = 0; kt < 12; kt++) {
                uint32_t a[4];
                LDSM_X4(a[0], a[1], a[2], a[3], aQ + kt * 32);
                #pragma unroll
                for (int g = 0; g < 4; g++) {
                    uint32_t b0, b1, b2, b3;
                    LDSM_X4(b0, b1, b2, b3, kB + (g * 16 * 200) * 2 + kt * 32);
                    uint32_t bb0[2] = {b0, b1}, bb1[2] = {b2, b3};
                    MMA_F16(s[2*g],   a, bb0);
                    MMA_F16(s[2*g+1], a, bb1);
                }
            }

            // ---- online softmax (log2 domain) ----
            const bool needmask = (n0 + 63 > q0 + wid * 16);
            const int colb = n0 + 2 * (lane & 3);
            float rm0 = -1e30f, rm1 = -1e30f;
            #pragma unroll
            for (int f = 0; f < 8; f++) {
                #pragma unroll
                for (int j = 0; j < 2; j++) {
                    int col = colb + f * 8 + j;
                    float z0 = s[f][j]     * sc2;
                    float z1 = s[f][2 + j] * sc2;
                    if (needmask) {
                        if (col > growA)     z0 = -1e30f;
                        if (col > growA + 8) z1 = -1e30f;
                    }
                    s[f][j] = z0; s[f][2 + j] = z1;
                    rm0 = fmaxf(rm0, z0); rm1 = fmaxf(rm1, z1);
                }
            }
            rm0 = fmaxf(rm0, __shfl_xor_sync(0xffffffffu, rm0, 1));
            rm0 = fmaxf(rm0, __shfl_xor_sync(0xffffffffu, rm0, 2));
            rm1 = fmaxf(rm1, __shfl_xor_sync(0xffffffffu, rm1, 1));
            rm1 = fmaxf(rm1, __shfl_xor_sync(0xffffffffu, rm1, 2));
            float mn0 = fmaxf(m0, rm0), mn1 = fmaxf(m1, rm1);
            float al0 = fexp2(m0 - mn0), al1 = fexp2(m1 - mn1);
            m0 = mn0; m1 = mn1;

            float rs0 = 0.f, rs1 = 0.f;
            #pragma unroll
            for (int f = 0; f < 8; f++) {
                #pragma unroll
                for (int j = 0; j < 2; j++) {
                    float p0 = fexp2(s[f][j]     - mn0);
                    float p1 = fexp2(s[f][2 + j] - mn1);
                    s[f][j] = p0; s[f][2 + j] = p1;
                    rs0 += p0; rs1 += p1;
                }
            }
            rs0 += __shfl_xor_sync(0xffffffffu, rs0, 1);
            rs0 += __shfl_xor_sync(0xffffffffu, rs0, 2);
            rs1 += __shfl_xor_sync(0xffffffffu, rs1, 1);
            rs1 += __shfl_xor_sync(0xffffffffu, rs1, 2);
            l0 = l0 * al0 + rs0;
            l1 = l1 * al1 + rs1;

            #pragma unroll
            for (int f = 0; f < 16; f++) {
                out[f][0] *= al0; out[f][1] *= al0;
                out[f][2] *= al1; out[f][3] *= al1;
            }

            // ---- O += P @ V (fp16) ----
            const uint32_t vB = sV + buf * (64 * 136 * 2)
                              + (((mat & 1) * 8 + r8) * 136 + (mat >> 1) * 8) * 2;
            #pragma unroll
            for (int kt = 0; kt < 4; kt++) {
                uint32_t pa[4];
                pa[0] = packh2(s[2*kt][0],   s[2*kt][1]);
                pa[1] = packh2(s[2*kt][2],   s[2*kt][3]);
                pa[2] = packh2(s[2*kt+1][0], s[2*kt+1][1]);
                pa[3] = packh2(s[2*kt+1][2], s[2*kt+1][3]);
                const uint32_t rowOff = (kt * 16 * 136) * 2;
                #pragma unroll
                for (int gv = 0; gv < 8; gv++) {
                    uint32_t h0, h1, h2, h3;
                    LDSM_X4T(h0, h1, h2, h3, vB + rowOff + gv * 32);
                    uint32_t bh0[2] = {h0, h1}, bh1[2] = {h2, h3};
                    MMA_F16(out[2*gv],   pa, bh0);
                    MMA_F16(out[2*gv+1], pa, bh1);
                }
            }
        }
        __syncthreads();
    }

    // ---- finalize ----
    float inv0 = 1.f / l0, inv1 = 1.f / l1;
    size_t r0g = (size_t)(b * SS + q0 + wid * 16 + (lane >> 2));
    size_t base0 = r0g * ODIM + h * VDIM + 2 * (lane & 3);
    size_t base1 = base0 + 8 * (size_t)ODIM;
    #pragma unroll
    for (int f = 0; f < 16; f++) {
        *(uint32_t*)&go[base0 + f * 8] = packh2(out[f][0] * inv0, out[f][1] * inv0);
        *(uint32_t*)&go[base1 + f * 8] = packh2(out[f][2] * inv1, out[f][3] * inv1);
    }
}

// ---------------- launcher ----------------
static inline void cvt_pass_s(const float* src, fp16* dst, size_t n, cudaStream_t st)
{
    int n4 = (int)(n / 4);
    cvt_fp16_k<<<(n4 + 255) / 256, 256, 0, st>>>((const float4*)src, (uint2*)dst, n4);
}

extern "C" void kernel_launch(void* const* d_in, const int* in_sizes, int n_in,
                              void* d_out, int out_size)
{
    const float* x     = (const float*)d_in[0];
    const float* fc    = (const float*)d_in[1];
    const float* wq_a  = (const float*)d_in[2];
    const float* qnw   = (const float*)d_in[3];
    const float* wq_b  = (const float*)d_in[4];
    const float* wkv_a = (const float*)d_in[5];
    const float* kvnw  = (const float*)d_in[6];
    const float* wkv_b = (const float*)d_in[7];
    const float* wo    = (const float*)d_in[8];
    float* out = (float*)d_out;

    float *cq, *c;
    fp16 *xf, *wqaf, *wqbf, *wkvaf, *wkvbf, *wof, *cqf, *kvnf, *af, *qb, *kb, *vb;
    cudaGetSymbolAddress((void**)&cq,   g_cq);
    cudaGetSymbolAddress((void**)&c,    g_c);
    cudaGetSymbolAddress((void**)&xf,   g_xf);
    cudaGetSymbolAddress((void**)&wqaf, g_wqaf);
    cudaGetSymbolAddress((void**)&wqbf, g_wqbf);
    cudaGetSymbolAddress((void**)&wkvaf,g_wkvaf);
    cudaGetSymbolAddress((void**)&wkvbf,g_wkvbf);
    cudaGetSymbolAddress((void**)&wof,  g_wof);
    cudaGetSymbolAddress((void**)&cqf,  g_cqf);
    cudaGetSymbolAddress((void**)&kvnf, g_kvnf);
    cudaGetSymbolAddress((void**)&af,   g_af);
    cudaGetSymbolAddress((void**)&qb,   g_qb);
    cudaGetSymbolAddress((void**)&kb,   g_kb);
    cudaGetSymbolAddress((void**)&vb,   g_vb);

    static cudaStream_t s1 = nullptr, s2 = nullptr;
    static cudaEvent_t eFork = nullptr, eJoin = nullptr;
    static cudaEvent_t eWqb = nullptr, eWkvb = nullptr, eWo = nullptr;
    if (s1 == nullptr) {
        cudaStreamCreateWithFlags(&s1, cudaStreamNonBlocking);
        cudaStreamCreateWithFlags(&s2, cudaStreamNonBlocking);
        cudaEventCreateWithFlags(&eFork, cudaEventDisableTiming);
        cudaEventCreateWithFlags(&eJoin, cudaEventDisableTiming);
        cudaEventCreateWithFlags(&eWqb,  cudaEventDisableTiming);
        cudaEventCreateWithFlags(&eWkvb, cudaEventDisableTiming);
        cudaEventCreateWithFlags(&eWo,   cudaEventDisableTiming);
    }
    cudaStream_t s0 = 0;

    const int smem128 = STAGES * (16384 + 128*128); // 98304
    const int smem64  = STAGES * (16384 + 64*128);  // 73728
    cudaFuncSetAttribute(gemm_fp16<128,0>, cudaFuncAttributeMaxDynamicSharedMemorySize, smem128);
    cudaFuncSetAttribute(gemm_fp16<128,1>, cudaFuncAttributeMaxDynamicSharedMemorySize, smem128);
    cudaFuncSetAttribute(gemm_fp16<128,2>, cudaFuncAttributeMaxDynamicSharedMemorySize, smem128);
    cudaFuncSetAttribute(gemm_fp16<64,0>,  cudaFuncAttributeMaxDynamicSharedMemorySize, smem64);
    cudaFuncSetAttribute(attn_mma, cudaFuncAttributeMaxDynamicSharedMemorySize, ATT_SMEM_BYTES);

    // ---- s0: x first (fork asap), then wq_a for GEMM1 ----
    cvt_pass_s(x,    xf,   (size_t)ROWS * NDIM, s0);
    cudaEventRecord(eFork, s0);                  // xf ready
    cvt_pass_s(wq_a, wqaf, (size_t)QRANK * NDIM, s0);

    // ---- s2: deferred weight conversions, each with its own ready-event ----
    cudaStreamWaitEvent(s2, eFork, 0);           // order after x-cvt bandwidth burst
    cvt_pass_s(wq_b,  wqbf,  (size_t)QDIM * QRANK, s2);
    cudaEventRecord(eWqb, s2);
    cvt_pass_s(wkv_b, wkvbf, (size_t)KVDIM * KVRANK, s2);
    cudaEventRecord(eWkvb, s2);
    cvt_pass_s(wo,    wof,   (size_t)NDIM * ODIM, s2);
    cudaEventRecord(eWo, s2);

    // ---- s1 (kv branch): GEMM4 -> rmsnorm -> kpe -> GEMM6 ----
    cudaStreamWaitEvent(s1, eFork, 0);
    cvt_pass_s(wkv_a, wkvaf, (size_t)CDIM * NDIM, s1);
    gemm_fp16<64,0><<<dim3(CDIM/64, ROWS/128), 256, smem64, s1>>>(
        xf, wkvaf, c, nullptr, nullptr, nullptr, ROWS, CDIM, NDIM);
    rmsnorm_cvt_k<<<ROWS, 256, 0, s1>>>(c, kvnf, kvnw, KVRANK, CDIM);
    kpe_conv_k<<<(NH*ROWS*32 + 255)/256, 256, 0, s1>>>(c, fc, kb);
    cudaStreamWaitEvent(s1, eWkvb, 0);
    gemm_fp16<128,2><<<dim3(KVDIM/128, ROWS/128), 256, smem128, s1>>>(
        kvnf, wkvbf, nullptr, kb, vb, nullptr, ROWS, KVDIM, KVRANK);
    cudaEventRecord(eJoin, s1);

    // ---- s0 (q branch): GEMM1 -> rmsnorm -> GEMM3 ----
    gemm_fp16<128,0><<<dim3(QRANK/128, ROWS/128), 256, smem128, s0>>>(
        xf, wqaf, cq, nullptr, nullptr, nullptr, ROWS, QRANK, NDIM);
    rmsnorm_cvt_k<<<ROWS, 256, 0, s0>>>(cq, cqf, qnw, QRANK, QRANK);
    cudaStreamWaitEvent(s0, eWqb, 0);
    gemm_fp16<128,1><<<dim3(QDIM/128, ROWS/128), 256, smem128, s0>>>(
        cqf, wqbf, nullptr, qb, nullptr, fc, ROWS, QDIM, QRANK);

    // ---- join, attention, output GEMM ----
    cudaStreamWaitEvent(s0, eJoin, 0);
    attn_mma<<<dim3(SS/128, NH, BB), 256, ATT_SMEM_BYTES, s0>>>(qb, kb, vb, af);
    cudaStreamWaitEvent(s0, eWo, 0);
    gemm_fp16<128,0><<<dim3(NDIM/128, ROWS/128), 256, smem128, s0>>>(
        af, wof, out, nullptr, nullptr, nullptr, ROWS, NDIM, ODIM);
}

// round 12
// speedup vs baseline: 1.2489x; 1.0904x over previous
#include <cuda_runtime.h>
#include <cuda_bf16.h>
#include <cuda_fp16.h>
#include <math.h>
#include <stdint.h>

// ---------------- problem constants ----------------
#define BB     2
#define SS     2048
#define NDIM   2048
#define NH     16
#define QRANK  1536
#define KVRANK 512
#define ROPE_D 64
#define NOPE_D 128
#define VDIM   128
#define QKH    192           // NOPE + ROPE
#define ROWS   (BB*SS)       // 4096
#define KVDIM  (NH*(NOPE_D+VDIM))  // 4096
#define QDIM   (NH*QKH)      // 3072
#define CDIM   (KVRANK+ROPE_D) // 576
#define ODIM   (NH*VDIM)     // 2048

typedef __half fp16;

// ---------------- scratch (device globals; no allocs allowed) ----------------
__device__ float g_cq [ROWS*QRANK];
__device__ float g_c  [ROWS*CDIM];
// fp16 operand planes
__device__ fp16 g_xf  [ROWS*NDIM];
__device__ fp16 g_wqaf[QRANK*NDIM];
__device__ fp16 g_wqbf[QDIM*QRANK];
__device__ fp16 g_wkvaf[CDIM*NDIM];
__device__ fp16 g_wkvbf[KVDIM*KVRANK];
__device__ fp16 g_wof [NDIM*ODIM];
__device__ fp16 g_cqf [ROWS*QRANK];
__device__ fp16 g_kvnf[ROWS*KVRANK];
__device__ fp16 g_af  [ROWS*ODIM];
// attention operands (head-major layouts)
__device__ fp16 g_qb [NH*ROWS*QKH];     // roped q
__device__ fp16 g_kb [NH*ROWS*QKH];     // k_nope | roped k_pe
__device__ fp16 g_vb [NH*ROWS*VDIM];    // v

// ---------------- helpers ----------------
__device__ __forceinline__ uint32_t packh2(float x, float y) {
    __half2 h = __floats2half2_rn(x, y);
    return *(uint32_t*)&h;
}

// fast exp2 on FMA pipe (x <= 0), rel err ~1e-6
__device__ __forceinline__ float fexp2(float x) {
    x = fmaxf(x, -126.f);
    float fl = floorf(x);
    float f = x - fl;
    float p = 1.535336188319500e-4f;
    p = fmaf(p, f, 1.339887440266574e-3f);
    p = fmaf(p, f, 9.618437357674640e-3f);
    p = fmaf(p, f, 5.550332471162809e-2f);
    p = fmaf(p, f, 2.402264791363012e-1f);
    p = fmaf(p, f, 6.931472028550421e-1f);
    p = fmaf(p, f, 1.0f);
    return p * __int_as_float(((int)fl + 127) << 23);
}

__global__ void cvt_fp16_k(const float4* __restrict__ in, uint2* __restrict__ out, int n4)
{
    int i = blockIdx.x * blockDim.x + threadIdx.x;
    if (i >= n4) return;
    float4 v = in[i];
    uint2 o;
    o.x = packh2(v.x, v.y);
    o.y = packh2(v.z, v.w);
    out[i] = o;
}

__device__ __forceinline__ uint32_t cvta_shared_u32(const void* p) {
    return (uint32_t)__cvta_generic_to_shared(p);
}

#define CP_ASYNC16(dst, src) \
    asm volatile("cp.async.cg.shared.global [%0], [%1], 16;" :: "r"(dst), "l"(src) : "memory")
#define CP_COMMIT() asm volatile("cp.async.commit_group;" ::: "memory")
#define CP_WAIT(N)  asm volatile("cp.async.wait_group %0;" :: "n"(N) : "memory")

#define LDSM_X4(r0,r1,r2,r3,addr) \
    asm volatile("ldmatrix.sync.aligned.m8n8.x4.shared.b16 {%0,%1,%2,%3}, [%4];" \
        : "=r"(r0), "=r"(r1), "=r"(r2), "=r"(r3) : "r"(addr))

#define LDSM_X4T(r0,r1,r2,r3,addr) \
    asm volatile("ldmatrix.sync.aligned.m8n8.x4.trans.shared.b16 {%0,%1,%2,%3}, [%4];" \
        : "=r"(r0), "=r"(r1), "=r"(r2), "=r"(r3) : "r"(addr))

#define MMA_F16(d, a, b) \
    asm volatile("mma.sync.aligned.m16n8k16.row.col.f32.f16.f16.f32 " \
        "{%0,%1,%2,%3}, {%4,%5,%6,%7}, {%8,%9}, {%0,%1,%2,%3};" \
        : "+f"((d)[0]), "+f"((d)[1]), "+f"((d)[2]), "+f"((d)[3]) \
        : "r"((a)[0]), "r"((a)[1]), "r"((a)[2]), "r"((a)[3]), "r"((b)[0]), "r"((b)[1]))

// ---------------- fp16 GEMM: C[M,N] = A[M,K] * B[N,K]^T (fp32 accum) ----------------
// CTA 128 x NT, K-chunk 64 (=128B fp16 row), XOR-8 swizzle, 3-stage cp.async ring,
// 2 CTAs/SM. 8 warps: 2(M) x 4(N), warp tile 64 x NT/4.
// MODE 0: write fp32 C. MODE 1: rope + fp16 head-major qb. MODE 2: fp16 kb/vb scatter.
#define STAGES 3

template<int NT>
__device__ __forceinline__ void load_stage(
    const fp16* __restrict__ A, const fp16* __restrict__ B,
    int K, int m0, int n0, int k0, uint32_t sA, int tid)
{
    constexpr int TOT = (128 + NT) * 8;
    #pragma unroll
    for (int i = 0; i < TOT / 256; i++) {
        int c = tid + i * 256;
        int row = c >> 3;
        int u = c & 7;               // 16B unit within 128B row
        if (row < 128) {
            const fp16* src = A + (size_t)(m0 + row) * K + k0 + u * 8;
            uint32_t dst = sA + row * 128 + ((u ^ (row & 7)) << 4);
            CP_ASYNC16(dst, src);
        } else {
            int br = row - 128;
            const fp16* src = B + (size_t)(n0 + br) * K + k0 + u * 8;
            uint32_t dst = sA + 16384 + br * 128 + ((u ^ (br & 7)) << 4);
            CP_ASYNC16(dst, src);
        }
    }
}

// mrow0: global row offset of A/C/O1/O2 region (for MODE 1 rope phase + scatter row)
template<int NT, int MODE>
__global__ __launch_bounds__(256, 2) void gemm_fp16(
    const fp16* __restrict__ A, const fp16* __restrict__ B,
    float* __restrict__ C, fp16* __restrict__ O1, fp16* __restrict__ O2,
    const float* __restrict__ fc, int M, int N, int K)
{
    constexpr int WN = NT / 4;
    constexpr int NI = WN / 8;
    constexpr int CHUNK = 16384 + NT * 128;

    extern __shared__ char smem_raw[];
    const uint32_t sbase = cvta_shared_u32(smem_raw);

    const int tid = threadIdx.x;
    const int wid = tid >> 5, lane = tid & 31;
    const int wm = wid >> 2, wn = wid & 3;
    const int m0 = blockIdx.y * 128;
    const int n0 = blockIdx.x * NT;
    const int mat = lane >> 3, r8 = lane & 7;

    float acc[4][NI][4];
    #pragma unroll
    for (int i = 0; i < 4; i++)
        #pragma unroll
        for (int j = 0; j < NI; j++)
            #pragma unroll
            for (int e = 0; e < 4; e++) acc[i][j][e] = 0.f;

    const int kT = K / 64;

    #pragma unroll
    for (int st = 0; st < STAGES - 1; st++) {
        load_stage<NT>(A, B, K, m0, n0, st * 64, sbase + st * CHUNK, tid);
        CP_COMMIT();
    }

    for (int it = 0; it < kT; it++) {
        CP_WAIT(STAGES - 2);
        __syncthreads();

        int nf = it + STAGES - 1;
        if (nf < kT)
            load_stage<NT>(A, B, K, m0, n0, nf * 64,
                           sbase + (nf % STAGES) * CHUNK, tid);
        CP_COMMIT();

        const uint32_t sA = sbase + (it % STAGES) * CHUNK;
        const uint32_t sB = sA + 16384;

        #pragma unroll
        for (int s = 0; s < 4; s++) {          // four k16 steps per 64-chunk
            const int kg = s * 2 + (mat >> 1);
            uint32_t a[4][4];
            uint32_t b[NI][2];

            #pragma unroll
            for (int mt = 0; mt < 4; mt++) {
                int row = wm * 64 + mt * 16 + (mat & 1) * 8 + r8;
                uint32_t rb = sA + row * 128;
                int x7 = row & 7;
                LDSM_X4(a[mt][0], a[mt][1], a[mt][2], a[mt][3],
                        rb + ((kg ^ x7) << 4));
            }
            #pragma unroll
            for (int p = 0; p < NI / 2; p++) {
                int row = wn * WN + p * 16 + (mat & 1) * 8 + r8;
                uint32_t rb = sB + row * 128;
                int x7 = row & 7;
                uint32_t t0, t1, t2, t3;
                LDSM_X4(t0, t1, t2, t3, rb + ((kg ^ x7) << 4));
                b[2*p][0] = t0; b[2*p][1] = t2;
                b[2*p+1][0] = t1; b[2*p+1][1] = t3;
            }

            #pragma unroll
            for (int mt = 0; mt < 4; mt++)
                #pragma unroll
                for (int nt = 0; nt < NI; nt++)
                    MMA_F16(acc[mt][nt], a[mt], b[nt]);
        }
    }

    const int qm = lane >> 2, qn = (lane & 3) * 2;
    #pragma unroll
    for (int mt = 0; mt < 4; mt++)
        #pragma unroll
        for (int nt = 0; nt < NI; nt++) {
            int m = m0 + wm * 64 + mt * 16 + qm;     // rows m, m+8
            int n = n0 + wn * WN + nt * 8 + qn;      // cols n, n+1 (n even)
            float v0 = acc[mt][nt][0], v1 = acc[mt][nt][1];
            float v2 = acc[mt][nt][2], v3 = acc[mt][nt][3];
            if (MODE == 0) {
                *(float2*)&C[(size_t)m * N + n]       = make_float2(v0, v1);
                *(float2*)&C[(size_t)(m + 8) * N + n] = make_float2(v2, v3);
            } else if (MODE == 1) {
                // q: rope on pe pairs, fp16 head-major
                int h = n / QKH, p2 = n % QKH;
                if (p2 >= NOPE_D) {
                    int pp = (p2 - NOPE_D) >> 1;
                    int s0 = m & (SS - 1), s8 = (m + 8) & (SS - 1);
                    float cs0 = fc[(s0 * 32 + pp) * 2], sn0 = fc[(s0 * 32 + pp) * 2 + 1];
                    float cs8 = fc[(s8 * 32 + pp) * 2], sn8 = fc[(s8 * 32 + pp) * 2 + 1];
                    float r0 = v0 * cs0 - v1 * sn0, i0 = v0 * sn0 + v1 * cs0;
                    float r2 = v2 * cs8 - v3 * sn8, i2 = v2 * sn8 + v3 * cs8;
                    v0 = r0; v1 = i0; v2 = r2; v3 = i2;
                }
                fp16* dst = O1 + ((size_t)h * ROWS + m) * QKH + p2;
                *(uint32_t*)dst               = packh2(v0, v1);
                *(uint32_t*)(dst + 8 * QKH)   = packh2(v2, v3);
            } else {
                // kv: scatter k_nope -> O1 (kb), v -> O2 (vb)
                int h = n >> 8, c2 = n & 255;
                if (c2 < NOPE_D) {
                    fp16* dst = O1 + ((size_t)h * ROWS + m) * QKH + c2;
                    *(uint32_t*)dst             = packh2(v0, v1);
                    *(uint32_t*)(dst + 8 * QKH) = packh2(v2, v3);
                } else {
                    fp16* dst = O2 + ((size_t)h * ROWS + m) * VDIM + (c2 - NOPE_D);
                    *(uint32_t*)dst              = packh2(v0, v1);
                    *(uint32_t*)(dst + 8 * VDIM) = packh2(v2, v3);
                }
            }
        }
}

// ---------------- RMSNorm -> fp16 plane ----------------
__global__ __launch_bounds__(256) void rmsnorm_cvt_k(
    const float* __restrict__ in, fp16* __restrict__ o,
    const float* __restrict__ w, int L, int sin)
{
    __shared__ float red[8];
    const int row = blockIdx.x;
    const float* ip = in + (size_t)row * sin;
    float ss = 0.f;
    for (int i = threadIdx.x; i < L; i += 256) {
        float v = ip[i];
        ss = fmaf(v, v, ss);
    }
    #pragma unroll
    for (int off = 16; off; off >>= 1)
        ss += __shfl_xor_sync(0xffffffffu, ss, off);
    if ((threadIdx.x & 31) == 0) red[threadIdx.x >> 5] = ss;
    __syncthreads();
    if (threadIdx.x == 0) {
        float tot = 0.f;
        #pragma unroll
        for (int i = 0; i < 8; i++) tot += red[i];
        red[0] = rsqrtf(tot / (float)L + 1e-6f);
    }
    __syncthreads();
    float inv = red[0];
    for (int i = threadIdx.x; i < L; i += 256)
        o[(size_t)row * L + i] = __float2half_rn(ip[i] * inv * w[i]);
}

// ---------------- k_pe conversion (rope; shared across heads) ----------------
__global__ void kpe_conv_k(const float* __restrict__ c, const float* __restrict__ fc,
                           fp16* __restrict__ kb)
{
    int idx = blockIdx.x * blockDim.x + threadIdx.x;
    if (idx >= NH * ROWS * 32) return;
    int p = idx & 31;
    int rowh = idx >> 5;
    int row = rowh & (ROWS - 1);
    int h = rowh >> 12;
    int s = row & (SS - 1);
    const float* src = c + (size_t)row * CDIM + KVRANK + 2 * p;
    float a = src[0], b = src[1];
    float cs = fc[(s * 32 + p) * 2 + 0];
    float sn = fc[(s * 32 + p) * 2 + 1];
    float v0 = a * cs - b * sn;
    float v1 = a * sn + b * cs;
    *(uint32_t*)(kb + ((size_t)h * ROWS + row) * QKH + NOPE_D + 2 * p) = packh2(v0, v1);
}

// ---------------- tensor-core flash attention (fp16), per-batch launch ----------------
// q-tile 128 rows, 8 warps x m16; key tiles 64; D=192. grid (SS/128, NH, 1).
#define ATT_SMEM_BYTES ((128*200 + 2*64*200 + 2*64*136) * 2)

__global__ __launch_bounds__(256, 1) void attn_mma(
    const fp16* __restrict__ gq, const fp16* __restrict__ gk,
    const fp16* __restrict__ gv, fp16* __restrict__ go, int b)
{
    extern __shared__ fp16 asm_[];
    const uint32_t sQ = cvta_shared_u32(asm_);
    const uint32_t sK = sQ + 128 * 200 * 2;
    const uint32_t sV = sK + 2 * 64 * 200 * 2;

    const int tid = threadIdx.x;
    const int wid = tid >> 5, lane = tid & 31;
    const int qt = gridDim.x - 1 - blockIdx.x;
    const int q0 = qt * 128;
    const int h  = blockIdx.y;
    const size_t hb = (size_t)h * ROWS + b * SS;

    {
        const fp16* qbase = gq + (hb + q0) * QKH;
        for (int i = tid; i < 3072; i += 256) {
            int row = i / 24, u = i - row * 24;
            CP_ASYNC16(sQ + (row * 200 + u * 8) * 2, qbase + row * QKH + u * 8);
        }
    }

    const int nT = q0 / 64 + 2;

    auto load_tile = [&](int n0, int buf) {
        const fp16* kbase = gk + (hb + n0) * QKH;
        uint32_t kd = sK + buf * (64 * 200 * 2);
        for (int i = tid; i < 1536; i += 256) {
            int row = i / 24, u = i - row * 24;
            CP_ASYNC16(kd + (row * 200 + u * 8) * 2, kbase + row * QKH + u * 8);
        }
        const fp16* vbase = gv + (hb + n0) * VDIM;
        uint32_t vd = sV + buf * (64 * 136 * 2);
        for (int i = tid; i < 1024; i += 256) {
            int row = i >> 4, u = i & 15;
            CP_ASYNC16(vd + (row * 136 + u * 8) * 2, vbase + row * VDIM + u * 8);
        }
    };

    load_tile(0, 0);
    CP_COMMIT();

    float out[16][4];
    #pragma unroll
    for (int f = 0; f < 16; f++)
        #pragma unroll
        for (int e = 0; e < 4; e++) out[f][e] = 0.f;
    float m0 = -1e30f, m1 = -1e30f, l0 = 0.f, l1 = 0.f;

    const int mat = lane >> 3, r8 = lane & 7;
    const uint32_t aQ = sQ + ((wid * 16 + (lane & 15)) * 200 + (lane >> 4) * 8) * 2;
    const float sc2 = 0.07216878364870323f * 1.4426950408889634f;
    const int growA = q0 + wid * 16 + (lane >> 2);

    for (int t = 0; t < nT; t++) {
        const int buf = t & 1;
        if (t + 1 < nT) load_tile(64 * (t + 1), buf ^ 1);
        CP_COMMIT();
        CP_WAIT(1);
        __syncthreads();

        const int n0 = 64 * t;
        const bool active = (n0 <= q0 + wid * 16 + 15);
        if (active) {
            // ---- S = Q @ K^T ----
            float s[8][4];
            #pragma unroll
            for (int f = 0; f < 8; f++)
                #pragma unroll
                for (int e = 0; e < 4; e++) s[f][e] = 0.f;

            const uint32_t kB = sK + buf * (64 * 200 * 2)
                              + (((mat >> 1) * 8 + r8) * 200 + (mat & 1) * 8) * 2;
            #pragma unroll
            for (int kt = 0; kt < 12; kt++) {
                uint32_t a[4];
                LDSM_X4(a[0], a[1], a[2], a[3], aQ + kt * 32);
                #pragma unroll
                for (int g = 0; g < 4; g++) {
                    uint32_t b0, b1, b2, b3;
                    LDSM_X4(b0, b1, b2, b3, kB + (g * 16 * 200) * 2 + kt * 32);
                    uint32_t bb0[2] = {b0, b1}, bb1[2] = {b2, b3};
                    MMA_F16(s[2*g],   a, bb0);
                    MMA_F16(s[2*g+1], a, bb1);
                }
            }

            // ---- online softmax (log2 domain) ----
            const bool needmask = (n0 + 63 > q0 + wid * 16);
            const int colb = n0 + 2 * (lane & 3);
            float rm0 = -1e30f, rm1 = -1e30f;
            #pragma unroll
            for (int f = 0; f < 8; f++) {
                #pragma unroll
                for (int j = 0; j < 2; j++) {
                    int col = colb + f * 8 + j;
                    float z0 = s[f][j]     * sc2;
                    float z1 = s[f][2 + j] * sc2;
                    if (needmask) {
                        if (col > growA)     z0 = -1e30f;
                        if (col > growA + 8) z1 = -1e30f;
                    }
                    s[f][j] = z0; s[f][2 + j] = z1;
                    rm0 = fmaxf(rm0, z0); rm1 = fmaxf(rm1, z1);
                }
            }
            rm0 = fmaxf(rm0, __shfl_xor_sync(0xffffffffu, rm0, 1));
            rm0 = fmaxf(rm0, __shfl_xor_sync(0xffffffffu, rm0, 2));
            rm1 = fmaxf(rm1, __shfl_xor_sync(0xffffffffu, rm1, 1));
            rm1 = fmaxf(rm1, __shfl_xor_sync(0xffffffffu, rm1, 2));
            float mn0 = fmaxf(m0, rm0), mn1 = fmaxf(m1, rm1);
            float al0 = fexp2(m0 - mn0), al1 = fexp2(m1 - mn1);
            m0 = mn0; m1 = mn1;

            float rs0 = 0.f, rs1 = 0.f;
            #pragma unroll
            for (int f = 0; f < 8; f++) {
                #pragma unroll
                for (int j = 0; j < 2; j++) {
                    float p0 = fexp2(s[f][j]     - mn0);
                    float p1 = fexp2(s[f][2 + j] - mn1);
                    s[f][j] = p0; s[f][2 + j] = p1;
                    rs0 += p0; rs1 += p1;
                }
            }
            rs0 += __shfl_xor_sync(0xffffffffu, rs0, 1);
            rs0 += __shfl_xor_sync(0xffffffffu, rs0, 2);
            rs1 += __shfl_xor_sync(0xffffffffu, rs1, 1);
            rs1 += __shfl_xor_sync(0xffffffffu, rs1, 2);
            l0 = l0 * al0 + rs0;
            l1 = l1 * al1 + rs1;

            #pragma unroll
            for (int f = 0; f < 16; f++) {
                out[f][0] *= al0; out[f][1] *= al0;
                out[f][2] *= al1; out[f][3] *= al1;
            }

            // ---- O += P @ V (fp16) ----
            const uint32_t vB = sV + buf * (64 * 136 * 2)
                              + (((mat & 1) * 8 + r8) * 136 + (mat >> 1) * 8) * 2;
            #pragma unroll
            for (int kt = 0; kt < 4; kt++) {
                uint32_t pa[4];
                pa[0] = packh2(s[2*kt][0],   s[2*kt][1]);
                pa[1] = packh2(s[2*kt][2],   s[2*kt][3]);
                pa[2] = packh2(s[2*kt+1][0], s[2*kt+1][1]);
                pa[3] = packh2(s[2*kt+1][2], s[2*kt+1][3]);
                const uint32_t rowOff = (kt * 16 * 136) * 2;
                #pragma unroll
                for (int gv = 0; gv < 8; gv++) {
                    uint32_t h0, h1, h2, h3;
                    LDSM_X4T(h0, h1, h2, h3, vB + rowOff + gv * 32);
                    uint32_t bh0[2] = {h0, h1}, bh1[2] = {h2, h3};
                    MMA_F16(out[2*gv],   pa, bh0);
                    MMA_F16(out[2*gv+1], pa, bh1);
                }
            }
        }
        __syncthreads();
    }

    // ---- finalize ----
    float inv0 = 1.f / l0, inv1 = 1.f / l1;
    size_t r0g = (size_t)(b * SS + q0 + wid * 16 + (lane >> 2));
    size_t base0 = r0g * ODIM + h * VDIM + 2 * (lane & 3);
    size_t base1 = base0 + 8 * (size_t)ODIM;
    #pragma unroll
    for (int f = 0; f < 16; f++) {
        *(uint32_t*)&go[base0 + f * 8] = packh2(out[f][0] * inv0, out[f][1] * inv0);
        *(uint32_t*)&go[base1 + f * 8] = packh2(out[f][2] * inv1, out[f][3] * inv1);
    }
}

// ---------------- launcher ----------------
static inline void cvt_pass_s(const float* src, fp16* dst, size_t n, cudaStream_t st)
{
    int n4 = (int)(n / 4);
    cvt_fp16_k<<<(n4 + 255) / 256, 256, 0, st>>>((const float4*)src, (uint2*)dst, n4);
}

extern "C" void kernel_launch(void* const* d_in, const int* in_sizes, int n_in,
                              void* d_out, int out_size)
{
    const float* x     = (const float*)d_in[0];
    const float* fc    = (const float*)d_in[1];
    const float* wq_a  = (const float*)d_in[2];
    const float* qnw   = (const float*)d_in[3];
    const float* wq_b  = (const float*)d_in[4];
    const float* wkv_a = (const float*)d_in[5];
    const float* kvnw  = (const float*)d_in[6];
    const float* wkv_b = (const float*)d_in[7];
    const float* wo    = (const float*)d_in[8];
    float* out = (float*)d_out;

    float *cq, *c;
    fp16 *xf, *wqaf, *wqbf, *wkvaf, *wkvbf, *wof, *cqf, *kvnf, *af, *qb, *kb, *vb;
    cudaGetSymbolAddress((void**)&cq,   g_cq);
    cudaGetSymbolAddress((void**)&c,    g_c);
    cudaGetSymbolAddress((void**)&xf,   g_xf);
    cudaGetSymbolAddress((void**)&wqaf, g_wqaf);
    cudaGetSymbolAddress((void**)&wqbf, g_wqbf);
    cudaGetSymbolAddress((void**)&wkvaf,g_wkvaf);
    cudaGetSymbolAddress((void**)&wkvbf,g_wkvbf);
    cudaGetSymbolAddress((void**)&wof,  g_wof);
    cudaGetSymbolAddress((void**)&cqf,  g_cqf);
    cudaGetSymbolAddress((void**)&kvnf, g_kvnf);
    cudaGetSymbolAddress((void**)&af,   g_af);
    cudaGetSymbolAddress((void**)&qb,   g_qb);
    cudaGetSymbolAddress((void**)&kb,   g_kb);
    cudaGetSymbolAddress((void**)&vb,   g_vb);

    static cudaStream_t s1 = nullptr, s2 = nullptr;
    static cudaEvent_t eFork = nullptr, eJoin = nullptr, eQb = nullptr, eS1 = nullptr;
    static cudaEvent_t eWqb = nullptr, eWkvb = nullptr, eWo = nullptr;
    if (s1 == nullptr) {
        cudaStreamCreateWithFlags(&s1, cudaStreamNonBlocking);
        cudaStreamCreateWithFlags(&s2, cudaStreamNonBlocking);
        cudaEventCreateWithFlags(&eFork, cudaEventDisableTiming);
        cudaEventCreateWithFlags(&eJoin, cudaEventDisableTiming);
        cudaEventCreateWithFlags(&eQb,   cudaEventDisableTiming);
        cudaEventCreateWithFlags(&eS1,   cudaEventDisableTiming);
        cudaEventCreateWithFlags(&eWqb,  cudaEventDisableTiming);
        cudaEventCreateWithFlags(&eWkvb, cudaEventDisableTiming);
        cudaEventCreateWithFlags(&eWo,   cudaEventDisableTiming);
    }
    cudaStream_t s0 = 0;

    const int smem128 = STAGES * (16384 + 128*128); // 98304
    const int smem64  = STAGES * (16384 + 64*128);  // 73728
    cudaFuncSetAttribute(gemm_fp16<128,0>, cudaFuncAttributeMaxDynamicSharedMemorySize, smem128);
    cudaFuncSetAttribute(gemm_fp16<128,1>, cudaFuncAttributeMaxDynamicSharedMemorySize, smem128);
    cudaFuncSetAttribute(gemm_fp16<128,2>, cudaFuncAttributeMaxDynamicSharedMemorySize, smem128);
    cudaFuncSetAttribute(gemm_fp16<64,0>,  cudaFuncAttributeMaxDynamicSharedMemorySize, smem64);
    cudaFuncSetAttribute(attn_mma, cudaFuncAttributeMaxDynamicSharedMemorySize, ATT_SMEM_BYTES);

    // ---- s0: x first (fork asap), then wq_a for GEMM1 ----
    cvt_pass_s(x,    xf,   (size_t)ROWS * NDIM, s0);
    cudaEventRecord(eFork, s0);                  // xf ready
    cvt_pass_s(wq_a, wqaf, (size_t)QRANK * NDIM, s0);

    // ---- s2: deferred weight conversions, each with its own ready-event ----
    cudaStreamWaitEvent(s2, eFork, 0);
    cvt_pass_s(wq_b,  wqbf,  (size_t)QDIM * QRANK, s2);
    cudaEventRecord(eWqb, s2);
    cvt_pass_s(wkv_b, wkvbf, (size_t)KVDIM * KVRANK, s2);
    cudaEventRecord(eWkvb, s2);
    cvt_pass_s(wo,    wof,   (size_t)NDIM * ODIM, s2);
    cudaEventRecord(eWo, s2);

    // ---- s1 (kv branch): GEMM4 -> rmsnorm -> kpe -> GEMM6 ----
    cudaStreamWaitEvent(s1, eFork, 0);
    cvt_pass_s(wkv_a, wkvaf, (size_t)CDIM * NDIM, s1);
    gemm_fp16<64,0><<<dim3(CDIM/64, ROWS/128), 256, smem64, s1>>>(
        xf, wkvaf, c, nullptr, nullptr, nullptr, ROWS, CDIM, NDIM);
    rmsnorm_cvt_k<<<ROWS, 256, 0, s1>>>(c, kvnf, kvnw, KVRANK, CDIM);
    kpe_conv_k<<<(NH*ROWS*32 + 255)/256, 256, 0, s1>>>(c, fc, kb);
    cudaStreamWaitEvent(s1, eWkvb, 0);
    gemm_fp16<128,2><<<dim3(KVDIM/128, ROWS/128), 256, smem128, s1>>>(
        kvnf, wkvbf, nullptr, kb, vb, nullptr, ROWS, KVDIM, KVRANK);
    cudaEventRecord(eJoin, s1);

    // ---- s0 (q branch): GEMM1 -> rmsnorm -> GEMM3 ----
    gemm_fp16<128,0><<<dim3(QRANK/128, ROWS/128), 256, smem128, s0>>>(
        xf, wqaf, cq, nullptr, nullptr, nullptr, ROWS, QRANK, NDIM);
    rmsnorm_cvt_k<<<ROWS, 256, 0, s0>>>(cq, cqf, qnw, QRANK, QRANK);
    cudaStreamWaitEvent(s0, eWqb, 0);
    gemm_fp16<128,1><<<dim3(QDIM/128, ROWS/128), 256, smem128, s0>>>(
        cqf, wqbf, nullptr, qb, nullptr, fc, ROWS, QDIM, QRANK);
    cudaEventRecord(eQb, s0);

    // ---- batch-pipelined tail: attn(b) -> gemm9(rows of b), b=0 on s0, b=1 on s1 ----
    cudaStreamWaitEvent(s0, eJoin, 0);           // s0 has qb; needs kb/vb
    attn_mma<<<dim3(SS/128, NH, 1), 256, ATT_SMEM_BYTES, s0>>>(qb, kb, vb, af, 0);
    cudaStreamWaitEvent(s0, eWo, 0);
    gemm_fp16<128,0><<<dim3(NDIM/128, SS/128), 256, smem128, s0>>>(
        af, wof, out, nullptr, nullptr, nullptr, SS, NDIM, ODIM);

    cudaStreamWaitEvent(s1, eQb, 0);             // s1 has kb/vb; needs qb
    attn_mma<<<dim3(SS/128, NH, 1), 256, ATT_SMEM_BYTES, s1>>>(qb, kb, vb, af, 1);
    cudaStreamWaitEvent(s1, eWo, 0);
    gemm_fp16<128,0><<<dim3(NDIM/128, SS/128), 256, smem128, s1>>>(
        af + (size_t)SS * ODIM, wof, out + (size_t)SS * NDIM,
        nullptr, nullptr, nullptr, SS, NDIM, ODIM);
    cudaEventRecord(eS1, s1);

    // join s1 back into the capture-origin stream
    cudaStreamWaitEvent(s0, eS1, 0);
}

// round 14
// speedup vs baseline: 1.2554x; 1.0052x over previous
#include <cuda_runtime.h>
#include <cuda_bf16.h>
#include <cuda_fp16.h>
#include <math.h>
#include <stdint.h>

// ---------------- problem constants ----------------
#define BB     2
#define SS     2048
#define NDIM   2048
#define NH     16
#define QRANK  1536
#define KVRANK 512
#define ROPE_D 64
#define NOPE_D 128
#define VDIM   128
#define QKH    192           // NOPE + ROPE
#define ROWS   (BB*SS)       // 4096
#define KVDIM  (NH*(NOPE_D+VDIM))  // 4096
#define QDIM   (NH*QKH)      // 3072
#define CDIM   (KVRANK+ROPE_D) // 576
#define ODIM   (NH*VDIM)     // 2048

typedef __half fp16;

// ---------------- scratch (device globals; no allocs allowed) ----------------
__device__ float g_cq [ROWS*QRANK];
__device__ float g_c  [ROWS*CDIM];
// fp16 operand planes
__device__ fp16 g_xf  [ROWS*NDIM];
__device__ fp16 g_wqaf[QRANK*NDIM];
__device__ fp16 g_wqbf[QDIM*QRANK];
__device__ fp16 g_wkvaf[CDIM*NDIM];
__device__ fp16 g_wkvbf[KVDIM*KVRANK];
__device__ fp16 g_wof [NDIM*ODIM];
__device__ fp16 g_cqf [ROWS*QRANK];
__device__ fp16 g_kvnf[ROWS*KVRANK];
__device__ fp16 g_af  [ROWS*ODIM];
// attention operands (head-major layouts)
__device__ fp16 g_qb [NH*ROWS*QKH];     // roped q
__device__ fp16 g_kb [NH*ROWS*QKH];     // k_nope | roped k_pe
__device__ fp16 g_vb [NH*ROWS*VDIM];    // v

// ---------------- helpers ----------------
__device__ __forceinline__ uint32_t packh2(float x, float y) {
    __half2 h = __floats2half2_rn(x, y);
    return *(uint32_t*)&h;
}

// fast exp2 on FMA pipe (x <= 0), rel err ~1e-6
__device__ __forceinline__ float fexp2(float x) {
    x = fmaxf(x, -126.f);
    float fl = floorf(x);
    float f = x - fl;
    float p = 1.535336188319500e-4f;
    p = fmaf(p, f, 1.339887440266574e-3f);
    p = fmaf(p, f, 9.618437357674640e-3f);
    p = fmaf(p, f, 5.550332471162809e-2f);
    p = fmaf(p, f, 2.402264791363012e-1f);
    p = fmaf(p, f, 6.931472028550421e-1f);
    p = fmaf(p, f, 1.0f);
    return p * __int_as_float(((int)fl + 127) << 23);
}

__global__ void cvt_fp16_k(const float4* __restrict__ in, uint2* __restrict__ out, int n4)
{
    int i = blockIdx.x * blockDim.x + threadIdx.x;
    if (i >= n4) return;
    float4 v = in[i];
    uint2 o;
    o.x = packh2(v.x, v.y);
    o.y = packh2(v.z, v.w);
    out[i] = o;
}

__device__ __forceinline__ uint32_t cvta_shared_u32(const void* p) {
    return (uint32_t)__cvta_generic_to_shared(p);
}

#define CP_ASYNC16(dst, src) \
    asm volatile("cp.async.cg.shared.global [%0], [%1], 16;" :: "r"(dst), "l"(src) : "memory")
#define CP_COMMIT() asm volatile("cp.async.commit_group;" ::: "memory")
#define CP_WAIT(N)  asm volatile("cp.async.wait_group %0;" :: "n"(N) : "memory")

#define LDSM_X4(r0,r1,r2,r3,addr) \
    asm volatile("ldmatrix.sync.aligned.m8n8.x4.shared.b16 {%0,%1,%2,%3}, [%4];" \
        : "=r"(r0), "=r"(r1), "=r"(r2), "=r"(r3) : "r"(addr))

#define LDSM_X4T(r0,r1,r2,r3,addr) \
    asm volatile("ldmatrix.sync.aligned.m8n8.x4.trans.shared.b16 {%0,%1,%2,%3}, [%4];" \
        : "=r"(r0), "=r"(r1), "=r"(r2), "=r"(r3) : "r"(addr))

#define MMA_F16(d, a, b) \
    asm volatile("mma.sync.aligned.m16n8k16.row.col.f32.f16.f16.f32 " \
        "{%0,%1,%2,%3}, {%4,%5,%6,%7}, {%8,%9}, {%0,%1,%2,%3};" \
        : "+f"((d)[0]), "+f"((d)[1]), "+f"((d)[2]), "+f"((d)[3]) \
        : "r"((a)[0]), "r"((a)[1]), "r"((a)[2]), "r"((a)[3]), "r"((b)[0]), "r"((b)[1]))

// ---------------- fp16 GEMM: C[M,N] = A[M,K] * B[N,K]^T (fp32 accum) ----------------
// CTA 128 x NT, K-chunk 64 (=128B fp16 row), XOR-8 swizzle, 3-stage cp.async ring,
// 2 CTAs/SM. 8 warps: 2(M) x 4(N), warp tile 64 x NT/4.
// MODE 0: write fp32 C. MODE 1: rope + fp16 head-major qb. MODE 2: fp16 kb/vb scatter.
// mrow0: global row offset of this launch's A/C slice (for MODE 1/2 scatter + rope phase).
#define STAGES 3

template<int NT>
__device__ __forceinline__ void load_stage(
    const fp16* __restrict__ A, const fp16* __restrict__ B,
    int K, int m0, int n0, int k0, uint32_t sA, int tid)
{
    constexpr int TOT = (128 + NT) * 8;
    #pragma unroll
    for (int i = 0; i < TOT / 256; i++) {
        int c = tid + i * 256;
        int row = c >> 3;
        int u = c & 7;               // 16B unit within 128B row
        if (row < 128) {
            const fp16* src = A + (size_t)(m0 + row) * K + k0 + u * 8;
            uint32_t dst = sA + row * 128 + ((u ^ (row & 7)) << 4);
            CP_ASYNC16(dst, src);
        } else {
            int br = row - 128;
            const fp16* src = B + (size_t)(n0 + br) * K + k0 + u * 8;
            uint32_t dst = sA + 16384 + br * 128 + ((u ^ (br & 7)) << 4);
            CP_ASYNC16(dst, src);
        }
    }
}

template<int NT, int MODE>
__global__ __launch_bounds__(256, 2) void gemm_fp16(
    const fp16* __restrict__ A, const fp16* __restrict__ B,
    float* __restrict__ C, fp16* __restrict__ O1, fp16* __restrict__ O2,
    const float* __restrict__ fc, int M, int N, int K, int mrow0)
{
    constexpr int WN = NT / 4;
    constexpr int NI = WN / 8;
    constexpr int CHUNK = 16384 + NT * 128;

    extern __shared__ char smem_raw[];
    const uint32_t sbase = cvta_shared_u32(smem_raw);

    const int tid = threadIdx.x;
    const int wid = tid >> 5, lane = tid & 31;
    const int wm = wid >> 2, wn = wid & 3;
    const int m0 = blockIdx.y * 128;
    const int n0 = blockIdx.x * NT;
    const int mat = lane >> 3, r8 = lane & 7;

    float acc[4][NI][4];
    #pragma unroll
    for (int i = 0; i < 4; i++)
        #pragma unroll
        for (int j = 0; j < NI; j++)
            #pragma unroll
            for (int e = 0; e < 4; e++) acc[i][j][e] = 0.f;

    const int kT = K / 64;

    #pragma unroll
    for (int st = 0; st < STAGES - 1; st++) {
        load_stage<NT>(A, B, K, m0, n0, st * 64, sbase + st * CHUNK, tid);
        CP_COMMIT();
    }

    for (int it = 0; it < kT; it++) {
        CP_WAIT(STAGES - 2);
        __syncthreads();

        int nf = it + STAGES - 1;
        if (nf < kT)
            load_stage<NT>(A, B, K, m0, n0, nf * 64,
                           sbase + (nf % STAGES) * CHUNK, tid);
        CP_COMMIT();

        const uint32_t sA = sbase + (it % STAGES) * CHUNK;
        const uint32_t sB = sA + 16384;

        #pragma unroll
        for (int s = 0; s < 4; s++) {          // four k16 steps per 64-chunk
            const int kg = s * 2 + (mat >> 1);
            uint32_t a[4][4];
            uint32_t b[NI][2];

            #pragma unroll
            for (int mt = 0; mt < 4; mt++) {
                int row = wm * 64 + mt * 16 + (mat & 1) * 8 + r8;
                uint32_t rb = sA + row * 128;
                int x7 = row & 7;
                LDSM_X4(a[mt][0], a[mt][1], a[mt][2], a[mt][3],
                        rb + ((kg ^ x7) << 4));
            }
            #pragma unroll
            for (int p = 0; p < NI / 2; p++) {
                int row = wn * WN + p * 16 + (mat & 1) * 8 + r8;
                uint32_t rb = sB + row * 128;
                int x7 = row & 7;
                uint32_t t0, t1, t2, t3;
                LDSM_X4(t0, t1, t2, t3, rb + ((kg ^ x7) << 4));
                b[2*p][0] = t0; b[2*p][1] = t2;
                b[2*p+1][0] = t1; b[2*p+1][1] = t3;
            }

            #pragma unroll
            for (int mt = 0; mt < 4; mt++)
                #pragma unroll
                for (int nt = 0; nt < NI; nt++)
                    MMA_F16(acc[mt][nt], a[mt], b[nt]);
        }
    }

    const int qm = lane >> 2, qn = (lane & 3) * 2;
    #pragma unroll
    for (int mt = 0; mt < 4; mt++)
        #pragma unroll
        for (int nt = 0; nt < NI; nt++) {
            int m = m0 + wm * 64 + mt * 16 + qm;     // local rows m, m+8
            int n = n0 + wn * WN + nt * 8 + qn;      // cols n, n+1 (n even)
            float v0 = acc[mt][nt][0], v1 = acc[mt][nt][1];
            float v2 = acc[mt][nt][2], v3 = acc[mt][nt][3];
            if (MODE == 0) {
                *(float2*)&C[(size_t)m * N + n]       = make_float2(v0, v1);
                *(float2*)&C[(size_t)(m + 8) * N + n] = make_float2(v2, v3);
            } else if (MODE == 1) {
                // q: rope on pe pairs, fp16 head-major; g = global row
                int g = mrow0 + m;
                int h = n / QKH, p2 = n % QKH;
                if (p2 >= NOPE_D) {
                    int pp = (p2 - NOPE_D) >> 1;
                    int s0 = g & (SS - 1), s8 = (g + 8) & (SS - 1);
                    float cs0 = fc[(s0 * 32 + pp) * 2], sn0 = fc[(s0 * 32 + pp) * 2 + 1];
                    float cs8 = fc[(s8 * 32 + pp) * 2], sn8 = fc[(s8 * 32 + pp) * 2 + 1];
                    float r0 = v0 * cs0 - v1 * sn0, i0 = v0 * sn0 + v1 * cs0;
                    float r2 = v2 * cs8 - v3 * sn8, i2 = v2 * sn8 + v3 * cs8;
                    v0 = r0; v1 = i0; v2 = r2; v3 = i2;
                }
                fp16* dst = O1 + ((size_t)h * ROWS + g) * QKH + p2;
                *(uint32_t*)dst               = packh2(v0, v1);
                *(uint32_t*)(dst + 8 * QKH)   = packh2(v2, v3);
            } else {
                // kv: scatter k_nope -> O1 (kb), v -> O2 (vb); g = global row
                int g = mrow0 + m;
                int h = n >> 8, c2 = n & 255;
                if (c2 < NOPE_D) {
                    fp16* dst = O1 + ((size_t)h * ROWS + g) * QKH + c2;
                    *(uint32_t*)dst             = packh2(v0, v1);
                    *(uint32_t*)(dst + 8 * QKH) = packh2(v2, v3);
                } else {
                    fp16* dst = O2 + ((size_t)h * ROWS + g) * VDIM + (c2 - NOPE_D);
                    *(uint32_t*)dst              = packh2(v0, v1);
                    *(uint32_t*)(dst + 8 * VDIM) = packh2(v2, v3);
                }
            }
        }
}

// ---------------- RMSNorm -> fp16 plane ----------------
__global__ __launch_bounds__(256) void rmsnorm_cvt_k(
    const float* __restrict__ in, fp16* __restrict__ o,
    const float* __restrict__ w, int L, int sin)
{
    __shared__ float red[8];
    const int row = blockIdx.x;
    const float* ip = in + (size_t)row * sin;
    float ss = 0.f;
    for (int i = threadIdx.x; i < L; i += 256) {
        float v = ip[i];
        ss = fmaf(v, v, ss);
    }
    #pragma unroll
    for (int off = 16; off; off >>= 1)
        ss += __shfl_xor_sync(0xffffffffu, ss, off);
    if ((threadIdx.x & 31) == 0) red[threadIdx.x >> 5] = ss;
    __syncthreads();
    if (threadIdx.x == 0) {
        float tot = 0.f;
        #pragma unroll
        for (int i = 0; i < 8; i++) tot += red[i];
        red[0] = rsqrtf(tot / (float)L + 1e-6f);
    }
    __syncthreads();
    float inv = red[0];
    for (int i = threadIdx.x; i < L; i += 256)
        o[(size_t)row * L + i] = __float2half_rn(ip[i] * inv * w[i]);
}

// ---------------- k_pe conversion (rope; shared across heads) ----------------
__global__ void kpe_conv_k(const float* __restrict__ c, const float* __restrict__ fc,
                           fp16* __restrict__ kb)
{
    int idx = blockIdx.x * blockDim.x + threadIdx.x;
    if (idx >= NH * ROWS * 32) return;
    int p = idx & 31;
    int rowh = idx >> 5;
    int row = rowh & (ROWS - 1);
    int h = rowh >> 12;
    int s = row & (SS - 1);
    const float* src = c + (size_t)row * CDIM + KVRANK + 2 * p;
    float a = src[0], b = src[1];
    float cs = fc[(s * 32 + p) * 2 + 0];
    float sn = fc[(s * 32 + p) * 2 + 1];
    float v0 = a * cs - b * sn;
    float v1 = a * sn + b * cs;
    *(uint32_t*)(kb + ((size_t)h * ROWS + row) * QKH + NOPE_D + 2 * p) = packh2(v0, v1);
}

// ---------------- tensor-core flash attention (fp16), per-batch launch ----------------
// q-tile 128 rows, 8 warps x m16; key tiles 64; D=192. grid (SS/128, NH, 1).
#define ATT_SMEM_BYTES ((128*200 + 2*64*200 + 2*64*136) * 2)

__global__ __launch_bounds__(256, 1) void attn_mma(
    const fp16* __restrict__ gq, const fp16* __restrict__ gk,
    const fp16* __restrict__ gv, fp16* __restrict__ go, int b)
{
    extern __shared__ fp16 asm_[];
    const uint32_t sQ = cvta_shared_u32(asm_);
    const uint32_t sK = sQ + 128 * 200 * 2;
    const uint32_t sV = sK + 2 * 64 * 200 * 2;

    const int tid = threadIdx.x;
    const int wid = tid >> 5, lane = tid & 31;
    const int qt = gridDim.x - 1 - blockIdx.x;
    const int q0 = qt * 128;
    const int h  = blockIdx.y;
    const size_t hb = (size_t)h * ROWS + b * SS;

    {
        const fp16* qbase = gq + (hb + q0) * QKH;
        for (int i = tid; i < 3072; i += 256) {
            int row = i / 24, u = i - row * 24;
            CP_ASYNC16(sQ + (row * 200 + u * 8) * 2, qbase + row * QKH + u * 8);
        }
    }

    const int nT = q0 / 64 + 2;

    auto load_tile = [&](int n0, int buf) {
        const fp16* kbase = gk + (hb + n0) * QKH;
        uint32_t kd = sK + buf * (64 * 200 * 2);
        for (int i = tid; i < 1536; i += 256) {
            int row = i / 24, u = i - row * 24;
            CP_ASYNC16(kd + (row * 200 + u * 8) * 2, kbase + row * QKH + u * 8);
        }
        const fp16* vbase = gv + (hb + n0) * VDIM;
        uint32_t vd = sV + buf * (64 * 136 * 2);
        for (int i = tid; i < 1024; i += 256) {
            int row = i >> 4, u = i & 15;
            CP_ASYNC16(vd + (row * 136 + u * 8) * 2, vbase + row * VDIM + u * 8);
        }
    };

    load_tile(0, 0);
    CP_COMMIT();

    float out[16][4];
    #pragma unroll
    for (int f = 0; f < 16; f++)
        #pragma unroll
        for (int e = 0; e < 4; e++) out[f][e] = 0.f;
    float m0 = -1e30f, m1 = -1e30f, l0 = 0.f, l1 = 0.f;

    const int mat = lane >> 3, r8 = lane & 7;
    const uint32_t aQ = sQ + ((wid * 16 + (lane & 15)) * 200 + (lane >> 4) * 8) * 2;
    const float sc2 = 0.07216878364870323f * 1.4426950408889634f;
    const int growA = q0 + wid * 16 + (lane >> 2);

    for (int t = 0; t < nT; t++) {
        const int buf = t & 1;
        if (t + 1 < nT) load_tile(64 * (t + 1), buf ^ 1);
        CP_COMMIT();
        CP_WAIT(1);
        __syncthreads();

        const int n0 = 64 * t;
        const bool active = (n0 <= q0 + wid * 16 + 15);
        if (active) {
            // ---- S = Q @ K^T ----
            float s[8][4];
            #pragma unroll
            for (int f = 0; f < 8; f++)
                #pragma unroll
                for (int e = 0; e < 4; e++) s[f][e] = 0.f;

            const uint32_t kB = sK + buf * (64 * 200 * 2)
                              + (((mat >> 1) * 8 + r8) * 200 + (mat & 1) * 8) * 2;
            #pragma unroll
            for (int kt = 0; kt < 12; kt++) {
                uint32_t a[4];
                LDSM_X4(a[0], a[1], a[2], a[3], aQ + kt * 32);
                #pragma unroll
                for (int g = 0; g < 4; g++) {
                    uint32_t b0, b1, b2, b3;
                    LDSM_X4(b0, b1, b2, b3, kB + (g * 16 * 200) * 2 + kt * 32);
                    uint32_t bb0[2] = {b0, b1}, bb1[2] = {b2, b3};
                    MMA_F16(s[2*g],   a, bb0);
                    MMA_F16(s[2*g+1], a, bb1);
                }
            }

            // ---- online softmax (log2 domain) ----
            const bool needmask = (n0 + 63 > q0 + wid * 16);
            const int colb = n0 + 2 * (lane & 3);
            float rm0 = -1e30f, rm1 = -1e30f;
            #pragma unroll
            for (int f = 0; f < 8; f++) {
                #pragma unroll
                for (int j = 0; j < 2; j++) {
                    int col = colb + f * 8 + j;
                    float z0 = s[f][j]     * sc2;
                    float z1 = s[f][2 + j] * sc2;
                    if (needmask) {
                        if (col > growA)     z0 = -1e30f;
                        if (col > growA + 8) z1 = -1e30f;
                    }
                    s[f][j] = z0; s[f][2 + j] = z1;
                    rm0 = fmaxf(rm0, z0); rm1 = fmaxf(rm1, z1);
                }
            }
            rm0 = fmaxf(rm0, __shfl_xor_sync(0xffffffffu, rm0, 1));
            rm0 = fmaxf(rm0, __shfl_xor_sync(0xffffffffu, rm0, 2));
            rm1 = fmaxf(rm1, __shfl_xor_sync(0xffffffffu, rm1, 1));
            rm1 = fmaxf(rm1, __shfl_xor_sync(0xffffffffu, rm1, 2));
            float mn0 = fmaxf(m0, rm0), mn1 = fmaxf(m1, rm1);
            float al0 = fexp2(m0 - mn0), al1 = fexp2(m1 - mn1);
            m0 = mn0; m1 = mn1;

            float rs0 = 0.f, rs1 = 0.f;
            #pragma unroll
            for (int f = 0; f < 8; f++) {
                #pragma unroll
                for (int j = 0; j < 2; j++) {
                    float p0 = fexp2(s[f][j]     - mn0);
                    float p1 = fexp2(s[f][2 + j] - mn1);
                    s[f][j] = p0; s[f][2 + j] = p1;
                    rs0 += p0; rs1 += p1;
                }
            }
            rs0 += __shfl_xor_sync(0xffffffffu, rs0, 1);
            rs0 += __shfl_xor_sync(0xffffffffu, rs0, 2);
            rs1 += __shfl_xor_sync(0xffffffffu, rs1, 1);
            rs1 += __shfl_xor_sync(0xffffffffu, rs1, 2);
            l0 = l0 * al0 + rs0;
            l1 = l1 * al1 + rs1;

            #pragma unroll
            for (int f = 0; f < 16; f++) {
                out[f][0] *= al0; out[f][1] *= al0;
                out[f][2] *= al1; out[f][3] *= al1;
            }

            // ---- O += P @ V (fp16) ----
            const uint32_t vB = sV + buf * (64 * 136 * 2)
                              + (((mat & 1) * 8 + r8) * 136 + (mat >> 1) * 8) * 2;
            #pragma unroll
            for (int kt = 0; kt < 4; kt++) {
                uint32_t pa[4];
                pa[0] = packh2(s[2*kt][0],   s[2*kt][1]);
                pa[1] = packh2(s[2*kt][2],   s[2*kt][3]);
                pa[2] = packh2(s[2*kt+1][0], s[2*kt+1][1]);
                pa[3] = packh2(s[2*kt+1][2], s[2*kt+1][3]);
                const uint32_t rowOff = (kt * 16 * 136) * 2;
                #pragma unroll
                for (int gv = 0; gv < 8; gv++) {
                    uint32_t h0, h1, h2, h3;
                    LDSM_X4T(h0, h1, h2, h3, vB + rowOff + gv * 32);
                    uint32_t bh0[2] = {h0, h1}, bh1[2] = {h2, h3};
                    MMA_F16(out[2*gv],   pa, bh0);
                    MMA_F16(out[2*gv+1], pa, bh1);
                }
            }
        }
        __syncthreads();
    }

    // ---- finalize ----
    float inv0 = 1.f / l0, inv1 = 1.f / l1;
    size_t r0g = (size_t)(b * SS + q0 + wid * 16 + (lane >> 2));
    size_t base0 = r0g * ODIM + h * VDIM + 2 * (lane & 3);
    size_t base1 = base0 + 8 * (size_t)ODIM;
    #pragma unroll
    for (int f = 0; f < 16; f++) {
        *(uint32_t*)&go[base0 + f * 8] = packh2(out[f][0] * inv0, out[f][1] * inv0);
        *(uint32_t*)&go[base1 + f * 8] = packh2(out[f][2] * inv1, out[f][3] * inv1);
    }
}

// ---------------- launcher ----------------
static inline void cvt_pass_s(const float* src, fp16* dst, size_t n, cudaStream_t st)
{
    int n4 = (int)(n / 4);
    cvt_fp16_k<<<(n4 + 255) / 256, 256, 0, st>>>((const float4*)src, (uint2*)dst, n4);
}

extern "C" void kernel_launch(void* const* d_in, const int* in_sizes, int n_in,
                              void* d_out, int out_size)
{
    const float* x     = (const float*)d_in[0];
    const float* fc    = (const float*)d_in[1];
    const float* wq_a  = (const float*)d_in[2];
    const float* qnw   = (const float*)d_in[3];
    const float* wq_b  = (const float*)d_in[4];
    const float* wkv_a = (const float*)d_in[5];
    const float* kvnw  = (const float*)d_in[6];
    const float* wkv_b = (const float*)d_in[7];
    const float* wo    = (const float*)d_in[8];
    float* out = (float*)d_out;

    float *cq, *c;
    fp16 *xf, *wqaf, *wqbf, *wkvaf, *wkvbf, *wof, *cqf, *kvnf, *af, *qb, *kb, *vb;
    cudaGetSymbolAddress((void**)&cq,   g_cq);
    cudaGetSymbolAddress((void**)&c,    g_c);
    cudaGetSymbolAddress((void**)&xf,   g_xf);
    cudaGetSymbolAddress((void**)&wqaf, g_wqaf);
    cudaGetSymbolAddress((void**)&wqbf, g_wqbf);
    cudaGetSymbolAddress((void**)&wkvaf,g_wkvaf);
    cudaGetSymbolAddress((void**)&wkvbf,g_wkvbf);
    cudaGetSymbolAddress((void**)&wof,  g_wof);
    cudaGetSymbolAddress((void**)&cqf,  g_cqf);
    cudaGetSymbolAddress((void**)&kvnf, g_kvnf);
    cudaGetSymbolAddress((void**)&af,   g_af);
    cudaGetSymbolAddress((void**)&qb,   g_qb);
    cudaGetSymbolAddress((void**)&kb,   g_kb);
    cudaGetSymbolAddress((void**)&vb,   g_vb);

    static cudaStream_t s1 = nullptr, s2 = nullptr;
    static cudaEvent_t eX = nullptr, eWqa = nullptr, eWqb = nullptr, eWkvb = nullptr;
    static cudaEvent_t eWo = nullptr, eKv0 = nullptr, eKv1 = nullptr, eS2 = nullptr;
    if (s1 == nullptr) {
        cudaStreamCreateWithFlags(&s1, cudaStreamNonBlocking);
        cudaStreamCreateWithFlags(&s2, cudaStreamNonBlocking);
        cudaEventCreateWithFlags(&eX,    cudaEventDisableTiming);
        cudaEventCreateWithFlags(&eWqa,  cudaEventDisableTiming);
        cudaEventCreateWithFlags(&eWqb,  cudaEventDisableTiming);
        cudaEventCreateWithFlags(&eWkvb, cudaEventDisableTiming);
        cudaEventCreateWithFlags(&eWo,   cudaEventDisableTiming);
        cudaEventCreateWithFlags(&eKv0,  cudaEventDisableTiming);
        cudaEventCreateWithFlags(&eKv1,  cudaEventDisableTiming);
        cudaEventCreateWithFlags(&eS2,   cudaEventDisableTiming);
    }
    cudaStream_t s0 = 0;

    const int smem128 = STAGES * (16384 + 128*128); // 98304
    const int smem64  = STAGES * (16384 + 64*128);  // 73728
    cudaFuncSetAttribute(gemm_fp16<128,0>, cudaFuncAttributeMaxDynamicSharedMemorySize, smem128);
    cudaFuncSetAttribute(gemm_fp16<128,1>, cudaFuncAttributeMaxDynamicSharedMemorySize, smem128);
    cudaFuncSetAttribute(gemm_fp16<128,2>, cudaFuncAttributeMaxDynamicSharedMemorySize, smem128);
    cudaFuncSetAttribute(gemm_fp16<64,0>,  cudaFuncAttributeMaxDynamicSharedMemorySize, smem64);
    cudaFuncSetAttribute(attn_mma, cudaFuncAttributeMaxDynamicSharedMemorySize, ATT_SMEM_BYTES);

    // NOTE on host issue order: in stream capture every cudaStreamWaitEvent must
    // be issued AFTER its cudaEventRecord (host order). Sections below are
    // topologically sorted accordingly.

    // ---- (1) s0: x, wq_a ----
    cvt_pass_s(x,    xf,   (size_t)ROWS * NDIM, s0);
    cudaEventRecord(eX, s0);
    cvt_pass_s(wq_a, wqaf, (size_t)QRANK * NDIM, s0);
    cudaEventRecord(eWqa, s0);

    // ---- (2) s2 part A: deferred weight cvts (records consumed later) ----
    cudaStreamWaitEvent(s2, eX, 0);
    cvt_pass_s(wq_b,  wqbf,  (size_t)QDIM * QRANK, s2);
    cudaEventRecord(eWqb, s2);
    cvt_pass_s(wkv_b, wkvbf, (size_t)KVDIM * KVRANK, s2);
    cudaEventRecord(eWkvb, s2);
    cvt_pass_s(wo,    wof,   (size_t)NDIM * ODIM, s2);
    cudaEventRecord(eWo, s2);

    // ---- (3) s1: kv branch (full GEMM4, per-batch GEMM6) ----
    cudaStreamWaitEvent(s1, eX, 0);
    cvt_pass_s(wkv_a, wkvaf, (size_t)CDIM * NDIM, s1);
    gemm_fp16<64,0><<<dim3(CDIM/64, ROWS/128), 256, smem64, s1>>>(
        xf, wkvaf, c, nullptr, nullptr, nullptr, ROWS, CDIM, NDIM, 0);
    rmsnorm_cvt_k<<<ROWS, 256, 0, s1>>>(c, kvnf, kvnw, KVRANK, CDIM);
    kpe_conv_k<<<(NH*ROWS*32 + 255)/256, 256, 0, s1>>>(c, fc, kb);
    cudaStreamWaitEvent(s1, eWkvb, 0);
    gemm_fp16<128,2><<<dim3(KVDIM/128, SS/128), 256, smem128, s1>>>(
        kvnf, wkvbf, nullptr, kb, vb, nullptr, SS, KVDIM, KVRANK, 0);
    cudaEventRecord(eKv0, s1);
    gemm_fp16<128,2><<<dim3(KVDIM/128, SS/128), 256, smem128, s1>>>(
        kvnf + (size_t)SS * KVRANK, wkvbf, nullptr, kb, vb, nullptr, SS, KVDIM, KVRANK, SS);
    cudaEventRecord(eKv1, s1);

    // ---- (4) s2 part B: full b1 chain ----
    cudaStreamWaitEvent(s2, eWqa, 0);
    gemm_fp16<128,0><<<dim3(QRANK/128, SS/128), 256, smem128, s2>>>(
        xf + (size_t)SS * NDIM, wqaf, cq + (size_t)SS * QRANK,
        nullptr, nullptr, nullptr, SS, QRANK, NDIM, 0);
    rmsnorm_cvt_k<<<SS, 256, 0, s2>>>(cq + (size_t)SS * QRANK, cqf + (size_t)SS * QRANK,
                                      qnw, QRANK, QRANK);
    gemm_fp16<128,1><<<dim3(QDIM/128, SS/128), 256, smem128, s2>>>(
        cqf + (size_t)SS * QRANK, wqbf, nullptr, qb, nullptr, fc, SS, QDIM, QRANK, SS);
    cudaStreamWaitEvent(s2, eKv1, 0);
    attn_mma<<<dim3(SS/128, NH, 1), 256, ATT_SMEM_BYTES, s2>>>(qb, kb, vb, af, 1);
    gemm_fp16<128,0><<<dim3(NDIM/128, SS/128), 256, smem128, s2>>>(
        af + (size_t)SS * ODIM, wof, out + (size_t)SS * NDIM,
        nullptr, nullptr, nullptr, SS, NDIM, ODIM, 0);
    cudaEventRecord(eS2, s2);

    // ---- (5) s0: b0 chain ----
    gemm_fp16<128,0><<<dim3(QRANK/128, SS/128), 256, smem128, s0>>>(
        xf, wqaf, cq, nullptr, nullptr, nullptr, SS, QRANK, NDIM, 0);
    rmsnorm_cvt_k<<<SS, 256, 0, s0>>>(cq, cqf, qnw, QRANK, QRANK);
    cudaStreamWaitEvent(s0, eWqb, 0);
    gemm_fp16<128,1><<<dim3(QDIM/128, SS/128), 256, smem128, s0>>>(
        cqf, wqbf, nullptr, qb, nullptr, fc, SS, QDIM, QRANK, 0);
    cudaStreamWaitEvent(s0, eKv0, 0);
    attn_mma<<<dim3(SS/128, NH, 1), 256, ATT_SMEM_BYTES, s0>>>(qb, kb, vb, af, 0);
    cudaStreamWaitEvent(s0, eWo, 0);
    gemm_fp16<128,0><<<dim3(NDIM/128, SS/128), 256, smem128, s0>>>(
        af, wof, out, nullptr, nullptr, nullptr, SS, NDIM, ODIM, 0);

    // join s2 back into the capture-origin stream
    cudaStreamWaitEvent(s0, eS2, 0);
}

// round 15
// speedup vs baseline: 1.2932x; 1.0301x over previous
#include <cuda_runtime.h>
#include <cuda_bf16.h>
#include <cuda_fp16.h>
#include <math.h>
#include <stdint.h>

// ---------------- problem constants ----------------
#define BB     2
#define SS     2048
#define NDIM   2048
#define NH     16
#define QRANK  1536
#define KVRANK 512
#define ROPE_D 64
#define NOPE_D 128
#define VDIM   128
#define QKH    192           // NOPE + ROPE
#define ROWS   (BB*SS)       // 4096
#define KVDIM  (NH*(NOPE_D+VDIM))  // 4096
#define QDIM   (NH*QKH)      // 3072
#define CDIM   (KVRANK+ROPE_D) // 576
#define ODIM   (NH*VDIM)     // 2048

typedef __half fp16;

// ---------------- scratch (device globals; no allocs allowed) ----------------
__device__ float g_cq [ROWS*QRANK];
__device__ float g_c  [ROWS*CDIM];
// fp16 operand planes
__device__ fp16 g_xf  [ROWS*NDIM];
__device__ fp16 g_wqaf[QRANK*NDIM];
__device__ fp16 g_wqbf[QDIM*QRANK];
__device__ fp16 g_wkvaf[CDIM*NDIM];
__device__ fp16 g_wkvbf[KVDIM*KVRANK];
__device__ fp16 g_wof [NDIM*ODIM];
__device__ fp16 g_cqf [ROWS*QRANK];
__device__ fp16 g_kvnf[ROWS*KVRANK];
__device__ fp16 g_af  [ROWS*ODIM];
// attention operands (head-major layouts)
__device__ fp16 g_qb [NH*ROWS*QKH];     // roped q
__device__ fp16 g_kb [NH*ROWS*QKH];     // k_nope | roped k_pe
__device__ fp16 g_vb [NH*ROWS*VDIM];    // v

// ---------------- helpers ----------------
__device__ __forceinline__ uint32_t packh2(float x, float y) {
    __half2 h = __floats2half2_rn(x, y);
    return *(uint32_t*)&h;
}

// fast exp2 on FMA pipe (x <= 0), rel err ~1e-6
__device__ __forceinline__ float fexp2(float x) {
    x = fmaxf(x, -126.f);
    float fl = floorf(x);
    float f = x - fl;
    float p = 1.535336188319500e-4f;
    p = fmaf(p, f, 1.339887440266574e-3f);
    p = fmaf(p, f, 9.618437357674640e-3f);
    p = fmaf(p, f, 5.550332471162809e-2f);
    p = fmaf(p, f, 2.402264791363012e-1f);
    p = fmaf(p, f, 6.931472028550421e-1f);
    p = fmaf(p, f, 1.0f);
    return p * __int_as_float(((int)fl + 127) << 23);
}

__global__ void cvt_fp16_k(const float4* __restrict__ in, uint2* __restrict__ out, int n4)
{
    int i = blockIdx.x * blockDim.x + threadIdx.x;
    if (i >= n4) return;
    float4 v = in[i];
    uint2 o;
    o.x = packh2(v.x, v.y);
    o.y = packh2(v.z, v.w);
    out[i] = o;
}

__device__ __forceinline__ uint32_t cvta_shared_u32(const void* p) {
    return (uint32_t)__cvta_generic_to_shared(p);
}

#define CP_ASYNC16(dst, src) \
    asm volatile("cp.async.cg.shared.global [%0], [%1], 16;" :: "r"(dst), "l"(src) : "memory")
#define CP_COMMIT() asm volatile("cp.async.commit_group;" ::: "memory")
#define CP_WAIT(N)  asm volatile("cp.async.wait_group %0;" :: "n"(N) : "memory")

#define LDSM_X4(r0,r1,r2,r3,addr) \
    asm volatile("ldmatrix.sync.aligned.m8n8.x4.shared.b16 {%0,%1,%2,%3}, [%4];" \
        : "=r"(r0), "=r"(r1), "=r"(r2), "=r"(r3) : "r"(addr))

#define LDSM_X4T(r0,r1,r2,r3,addr) \
    asm volatile("ldmatrix.sync.aligned.m8n8.x4.trans.shared.b16 {%0,%1,%2,%3}, [%4];" \
        : "=r"(r0), "=r"(r1), "=r"(r2), "=r"(r3) : "r"(addr))

#define MMA_F16(d, a, b) \
    asm volatile("mma.sync.aligned.m16n8k16.row.col.f32.f16.f16.f32 " \
        "{%0,%1,%2,%3}, {%4,%5,%6,%7}, {%8,%9}, {%0,%1,%2,%3};" \
        : "+f"((d)[0]), "+f"((d)[1]), "+f"((d)[2]), "+f"((d)[3]) \
        : "r"((a)[0]), "r"((a)[1]), "r"((a)[2]), "r"((a)[3]), "r"((b)[0]), "r"((b)[1]))

// ---------------- fp16 GEMM: C[M,N] = A[M,K] * B[N,K]^T (fp32 accum) ----------------
// CTA 128 x NT, K-chunk 64 (=128B fp16 row), XOR-8 swizzle, 3-stage cp.async ring,
// 2 CTAs/SM. 8 warps: 2(M) x 4(N), warp tile 64 x NT/4.
// MODE 0: write fp32 C. MODE 1: rope + fp16 head-major qb. MODE 2: fp16 kb/vb scatter.
// mrow0: global row offset of this launch's A/C slice (for MODE 1/2 scatter + rope phase).
#define STAGES 3

template<int NT>
__device__ __forceinline__ void load_stage(
    const fp16* __restrict__ A, const fp16* __restrict__ B,
    int K, int m0, int n0, int k0, uint32_t sA, int tid)
{
    constexpr int TOT = (128 + NT) * 8;
    #pragma unroll
    for (int i = 0; i < TOT / 256; i++) {
        int c = tid + i * 256;
        int row = c >> 3;
        int u = c & 7;               // 16B unit within 128B row
        if (row < 128) {
            const fp16* src = A + (size_t)(m0 + row) * K + k0 + u * 8;
            uint32_t dst = sA + row * 128 + ((u ^ (row & 7)) << 4);
            CP_ASYNC16(dst, src);
        } else {
            int br = row - 128;
            const fp16* src = B + (size_t)(n0 + br) * K + k0 + u * 8;
            uint32_t dst = sA + 16384 + br * 128 + ((u ^ (br & 7)) << 4);
            CP_ASYNC16(dst, src);
        }
    }
}

template<int NT, int MODE>
__global__ __launch_bounds__(256, 2) void gemm_fp16(
    const fp16* __restrict__ A, const fp16* __restrict__ B,
    float* __restrict__ C, fp16* __restrict__ O1, fp16* __restrict__ O2,
    const float* __restrict__ fc, int M, int N, int K, int mrow0)
{
    constexpr int WN = NT / 4;
    constexpr int NI = WN / 8;
    constexpr int CHUNK = 16384 + NT * 128;

    extern __shared__ char smem_raw[];
    const uint32_t sbase = cvta_shared_u32(smem_raw);

    const int tid = threadIdx.x;
    const int wid = tid >> 5, lane = tid & 31;
    const int wm = wid >> 2, wn = wid & 3;
    const int m0 = blockIdx.y * 128;
    const int n0 = blockIdx.x * NT;
    const int mat = lane >> 3, r8 = lane & 7;

    float acc[4][NI][4];
    #pragma unroll
    for (int i = 0; i < 4; i++)
        #pragma unroll
        for (int j = 0; j < NI; j++)
            #pragma unroll
            for (int e = 0; e < 4; e++) acc[i][j][e] = 0.f;

    const int kT = K / 64;

    #pragma unroll
    for (int st = 0; st < STAGES - 1; st++) {
        load_stage<NT>(A, B, K, m0, n0, st * 64, sbase + st * CHUNK, tid);
        CP_COMMIT();
    }

    for (int it = 0; it < kT; it++) {
        CP_WAIT(STAGES - 2);
        __syncthreads();

        int nf = it + STAGES - 1;
        if (nf < kT)
            load_stage<NT>(A, B, K, m0, n0, nf * 64,
                           sbase + (nf % STAGES) * CHUNK, tid);
        CP_COMMIT();

        const uint32_t sA = sbase + (it % STAGES) * CHUNK;
        const uint32_t sB = sA + 16384;

        #pragma unroll
        for (int s = 0; s < 4; s++) {          // four k16 steps per 64-chunk
            const int kg = s * 2 + (mat >> 1);
            uint32_t a[4][4];
            uint32_t b[NI][2];

            #pragma unroll
            for (int mt = 0; mt < 4; mt++) {
                int row = wm * 64 + mt * 16 + (mat & 1) * 8 + r8;
                uint32_t rb = sA + row * 128;
                int x7 = row & 7;
                LDSM_X4(a[mt][0], a[mt][1], a[mt][2], a[mt][3],
                        rb + ((kg ^ x7) << 4));
            }
            #pragma unroll
            for (int p = 0; p < NI / 2; p++) {
                int row = wn * WN + p * 16 + (mat & 1) * 8 + r8;
                uint32_t rb = sB + row * 128;
                int x7 = row & 7;
                uint32_t t0, t1, t2, t3;
                LDSM_X4(t0, t1, t2, t3, rb + ((kg ^ x7) << 4));
                b[2*p][0] = t0; b[2*p][1] = t2;
                b[2*p+1][0] = t1; b[2*p+1][1] = t3;
            }

            #pragma unroll
            for (int mt = 0; mt < 4; mt++)
                #pragma unroll
                for (int nt = 0; nt < NI; nt++)
                    MMA_F16(acc[mt][nt], a[mt], b[nt]);
        }
    }

    const int qm = lane >> 2, qn = (lane & 3) * 2;
    #pragma unroll
    for (int mt = 0; mt < 4; mt++)
        #pragma unroll
        for (int nt = 0; nt < NI; nt++) {
            int m = m0 + wm * 64 + mt * 16 + qm;     // local rows m, m+8
            int n = n0 + wn * WN + nt * 8 + qn;      // cols n, n+1 (n even)
            float v0 = acc[mt][nt][0], v1 = acc[mt][nt][1];
            float v2 = acc[mt][nt][2], v3 = acc[mt][nt][3];
            if (MODE == 0) {
                *(float2*)&C[(size_t)m * N + n]       = make_float2(v0, v1);
                *(float2*)&C[(size_t)(m + 8) * N + n] = make_float2(v2, v3);
            } else if (MODE == 1) {
                // q: rope on pe pairs, fp16 head-major; g = global row
                int g = mrow0 + m;
                int h = n / QKH, p2 = n % QKH;
                if (p2 >= NOPE_D) {
                    int pp = (p2 - NOPE_D) >> 1;
                    int s0 = g & (SS - 1), s8 = (g + 8) & (SS - 1);
                    float cs0 = fc[(s0 * 32 + pp) * 2], sn0 = fc[(s0 * 32 + pp) * 2 + 1];
                    float cs8 = fc[(s8 * 32 + pp) * 2], sn8 = fc[(s8 * 32 + pp) * 2 + 1];
                    float r0 = v0 * cs0 - v1 * sn0, i0 = v0 * sn0 + v1 * cs0;
                    float r2 = v2 * cs8 - v3 * sn8, i2 = v2 * sn8 + v3 * cs8;
                    v0 = r0; v1 = i0; v2 = r2; v3 = i2;
                }
                fp16* dst = O1 + ((size_t)h * ROWS + g) * QKH + p2;
                *(uint32_t*)dst               = packh2(v0, v1);
                *(uint32_t*)(dst + 8 * QKH)   = packh2(v2, v3);
            } else {
                // kv: scatter k_nope -> O1 (kb), v -> O2 (vb); g = global row
                int g = mrow0 + m;
                int h = n >> 8, c2 = n & 255;
                if (c2 < NOPE_D) {
                    fp16* dst = O1 + ((size_t)h * ROWS + g) * QKH + c2;
                    *(uint32_t*)dst             = packh2(v0, v1);
                    *(uint32_t*)(dst + 8 * QKH) = packh2(v2, v3);
                } else {
                    fp16* dst = O2 + ((size_t)h * ROWS + g) * VDIM + (c2 - NOPE_D);
                    *(uint32_t*)dst              = packh2(v0, v1);
                    *(uint32_t*)(dst + 8 * VDIM) = packh2(v2, v3);
                }
            }
        }
}

// ---------------- RMSNorm -> fp16 plane ----------------
__global__ __launch_bounds__(256) void rmsnorm_cvt_k(
    const float* __restrict__ in, fp16* __restrict__ o,
    const float* __restrict__ w, int L, int sin)
{
    __shared__ float red[8];
    const int row = blockIdx.x;
    const float* ip = in + (size_t)row * sin;
    float ss = 0.f;
    for (int i = threadIdx.x; i < L; i += 256) {
        float v = ip[i];
        ss = fmaf(v, v, ss);
    }
    #pragma unroll
    for (int off = 16; off; off >>= 1)
        ss += __shfl_xor_sync(0xffffffffu, ss, off);
    if ((threadIdx.x & 31) == 0) red[threadIdx.x >> 5] = ss;
    __syncthreads();
    if (threadIdx.x == 0) {
        float tot = 0.f;
        #pragma unroll
        for (int i = 0; i < 8; i++) tot += red[i];
        red[0] = rsqrtf(tot / (float)L + 1e-6f);
    }
    __syncthreads();
    float inv = red[0];
    for (int i = threadIdx.x; i < L; i += 256)
        o[(size_t)row * L + i] = __float2half_rn(ip[i] * inv * w[i]);
}

// ---------------- k_pe conversion (rope; shared across heads) ----------------
__global__ void kpe_conv_k(const float* __restrict__ c, const float* __restrict__ fc,
                           fp16* __restrict__ kb)
{
    int idx = blockIdx.x * blockDim.x + threadIdx.x;
    if (idx >= NH * ROWS * 32) return;
    int p = idx & 31;
    int rowh = idx >> 5;
    int row = rowh & (ROWS - 1);
    int h = rowh >> 12;
    int s = row & (SS - 1);
    const float* src = c + (size_t)row * CDIM + KVRANK + 2 * p;
    float a = src[0], b = src[1];
    float cs = fc[(s * 32 + p) * 2 + 0];
    float sn = fc[(s * 32 + p) * 2 + 1];
    float v0 = a * cs - b * sn;
    float v1 = a * sn + b * cs;
    *(uint32_t*)(kb + ((size_t)h * ROWS + row) * QKH + NOPE_D + 2 * p) = packh2(v0, v1);
}

// ---------------- tensor-core flash attention (fp16), per-batch launch ----------------
// q-tile 64 rows, 4 warps x m16 (128 threads), 2 CTAs/SM; key tiles 64; D=192.
// smem (fp16): Q 64x200, K[2] 64x200, V[2] 64x136 = 111616 B -> 2 CTAs fit 228KB/SM.
// grid (SS/64, NH, 1).
#define ATT_SMEM_BYTES ((64*200 + 2*64*200 + 2*64*136) * 2)

__global__ __launch_bounds__(128, 2) void attn_mma(
    const fp16* __restrict__ gq, const fp16* __restrict__ gk,
    const fp16* __restrict__ gv, fp16* __restrict__ go, int b)
{
    extern __shared__ fp16 asm_[];
    const uint32_t sQ = cvta_shared_u32(asm_);
    const uint32_t sK = sQ + 64 * 200 * 2;
    const uint32_t sV = sK + 2 * 64 * 200 * 2;

    const int tid = threadIdx.x;
    const int wid = tid >> 5, lane = tid & 31;
    const int qt = gridDim.x - 1 - blockIdx.x;   // reversed: biggest work first
    const int q0 = qt * 64;
    const int h  = blockIdx.y;
    const size_t hb = (size_t)h * ROWS + b * SS;

    // Q tile: 64 rows x 24 16B-units over 128 threads
    {
        const fp16* qbase = gq + (hb + q0) * QKH;
        for (int i = tid; i < 1536; i += 128) {
            int row = i / 24, u = i - row * 24;
            CP_ASYNC16(sQ + (row * 200 + u * 8) * 2, qbase + row * QKH + u * 8);
        }
    }

    const int nT = qt + 1;

    auto load_tile = [&](int n0, int buf) {
        const fp16* kbase = gk + (hb + n0) * QKH;
        uint32_t kd = sK + buf * (64 * 200 * 2);
        for (int i = tid; i < 1536; i += 128) {
            int row = i / 24, u = i - row * 24;
            CP_ASYNC16(kd + (row * 200 + u * 8) * 2, kbase + row * QKH + u * 8);
        }
        const fp16* vbase = gv + (hb + n0) * VDIM;
        uint32_t vd = sV + buf * (64 * 136 * 2);
        for (int i = tid; i < 1024; i += 128) {
            int row = i >> 4, u = i & 15;
            CP_ASYNC16(vd + (row * 136 + u * 8) * 2, vbase + row * VDIM + u * 8);
        }
    };

    load_tile(0, 0);
    CP_COMMIT();

    float out[16][4];
    #pragma unroll
    for (int f = 0; f < 16; f++)
        #pragma unroll
        for (int e = 0; e < 4; e++) out[f][e] = 0.f;
    float m0 = -1e30f, m1 = -1e30f, l0 = 0.f, l1 = 0.f;

    const int mat = lane >> 3, r8 = lane & 7;
    const uint32_t aQ = sQ + ((wid * 16 + (lane & 15)) * 200 + (lane >> 4) * 8) * 2;
    const float sc2 = 0.07216878364870323f * 1.4426950408889634f;
    const int growA = q0 + wid * 16 + (lane >> 2);

    for (int t = 0; t < nT; t++) {
        const int buf = t & 1;
        if (t + 1 < nT) load_tile(64 * (t + 1), buf ^ 1);
        CP_COMMIT();
        CP_WAIT(1);
        __syncthreads();

        const int n0 = 64 * t;
        {
            // ---- S = Q @ K^T ----
            float s[8][4];
            #pragma unroll
            for (int f = 0; f < 8; f++)
                #pragma unroll
                for (int e = 0; e < 4; e++) s[f][e] = 0.f;

            const uint32_t kB = sK + buf * (64 * 200 * 2)
                              + (((mat >> 1) * 8 + r8) * 200 + (mat & 1) * 8) * 2;
            #pragma unroll
            for (int kt = 0; kt < 12; kt++) {
                uint32_t a[4];
                LDSM_X4(a[0], a[1], a[2], a[3], aQ + kt * 32);
                #pragma unroll
                for (int g = 0; g < 4; g++) {
                    uint32_t b0, b1, b2, b3;
                    LDSM_X4(b0, b1, b2, b3, kB + (g * 16 * 200) * 2 + kt * 32);
                    uint32_t bb0[2] = {b0, b1}, bb1[2] = {b2, b3};
                    MMA_F16(s[2*g],   a, bb0);
                    MMA_F16(s[2*g+1], a, bb1);
                }
            }

            // ---- online softmax (log2 domain) ----
            const bool needmask = (n0 + 63 > q0 + wid * 16);
            const int colb = n0 + 2 * (lane & 3);
            float rm0 = -1e30f, rm1 = -1e30f;
            #pragma unroll
            for (int f = 0; f < 8; f++) {
                #pragma unroll
                for (int j = 0; j < 2; j++) {
                    int col = colb + f * 8 + j;
                    float z0 = s[f][j]     * sc2;
                    float z1 = s[f][2 + j] * sc2;
                    if (needmask) {
                        if (col > growA)     z0 = -1e30f;
                        if (col > growA + 8) z1 = -1e30f;
                    }
                    s[f][j] = z0; s[f][2 + j] = z1;
                    rm0 = fmaxf(rm0, z0); rm1 = fmaxf(rm1, z1);
                }
            }
            rm0 = fmaxf(rm0, __shfl_xor_sync(0xffffffffu, rm0, 1));
            rm0 = fmaxf(rm0, __shfl_xor_sync(0xffffffffu, rm0, 2));
            rm1 = fmaxf(rm1, __shfl_xor_sync(0xffffffffu, rm1, 1));
            rm1 = fmaxf(rm1, __shfl_xor_sync(0xffffffffu, rm1, 2));
            float mn0 = fmaxf(m0, rm0), mn1 = fmaxf(m1, rm1);
            float al0 = fexp2(m0 - mn0), al1 = fexp2(m1 - mn1);
            m0 = mn0; m1 = mn1;

            float rs0 = 0.f, rs1 = 0.f;
            #pragma unroll
            for (int f = 0; f < 8; f++) {
                #pragma unroll
                for (int j = 0; j < 2; j++) {
                    float p0 = fexp2(s[f][j]     - mn0);
                    float p1 = fexp2(s[f][2 + j] - mn1);
                    s[f][j] = p0; s[f][2 + j] = p1;
                    rs0 += p0; rs1 += p1;
                }
            }
            rs0 += __shfl_xor_sync(0xffffffffu, rs0, 1);
            rs0 += __shfl_xor_sync(0xffffffffu, rs0, 2);
            rs1 += __shfl_xor_sync(0xffffffffu, rs1, 1);
            rs1 += __shfl_xor_sync(0xffffffffu, rs1, 2);
            l0 = l0 * al0 + rs0;
            l1 = l1 * al1 + rs1;

            #pragma unroll
            for (int f = 0; f < 16; f++) {
                out[f][0] *= al0; out[f][1] *= al0;
                out[f][2] *= al1; out[f][3] *= al1;
            }

            // ---- O += P @ V (fp16) ----
            const uint32_t vB = sV + buf * (64 * 136 * 2)
                              + (((mat & 1) * 8 + r8) * 136 + (mat >> 1) * 8) * 2;
            #pragma unroll
            for (int kt = 0; kt < 4; kt++) {
                uint32_t pa[4];
                pa[0] = packh2(s[2*kt][0],   s[2*kt][1]);
                pa[1] = packh2(s[2*kt][2],   s[2*kt][3]);
                pa[2] = packh2(s[2*kt+1][0], s[2*kt+1][1]);
                pa[3] = packh2(s[2*kt+1][2], s[2*kt+1][3]);
                const uint32_t rowOff = (kt * 16 * 136) * 2;
                #pragma unroll
                for (int gv = 0; gv < 8; gv++) {
                    uint32_t h0, h1, h2, h3;
                    LDSM_X4T(h0, h1, h2, h3, vB + rowOff + gv * 32);
                    uint32_t bh0[2] = {h0, h1}, bh1[2] = {h2, h3};
                    MMA_F16(out[2*gv],   pa, bh0);
                    MMA_F16(out[2*gv+1], pa, bh1);
                }
            }
        }
        __syncthreads();
    }

    // ---- finalize ----
    float inv0 = 1.f / l0, inv1 = 1.f / l1;
    size_t r0g = (size_t)(b * SS + q0 + wid * 16 + (lane >> 2));
    size_t base0 = r0g * ODIM + h * VDIM + 2 * (lane & 3);
    size_t base1 = base0 + 8 * (size_t)ODIM;
    #pragma unroll
    for (int f = 0; f < 16; f++) {
        *(uint32_t*)&go[base0 + f * 8] = packh2(out[f][0] * inv0, out[f][1] * inv0);
        *(uint32_t*)&go[base1 + f * 8] = packh2(out[f][2] * inv1, out[f][3] * inv1);
    }
}

// ---------------- launcher ----------------
static inline void cvt_pass_s(const float* src, fp16* dst, size_t n, cudaStream_t st)
{
    int n4 = (int)(n / 4);
    cvt_fp16_k<<<(n4 + 255) / 256, 256, 0, st>>>((const float4*)src, (uint2*)dst, n4);
}

extern "C" void kernel_launch(void* const* d_in, const int* in_sizes, int n_in,
                              void* d_out, int out_size)
{
    const float* x     = (const float*)d_in[0];
    const float* fc    = (const float*)d_in[1];
    const float* wq_a  = (const float*)d_in[2];
    const float* qnw   = (const float*)d_in[3];
    const float* wq_b  = (const float*)d_in[4];
    const float* wkv_a = (const float*)d_in[5];
    const float* kvnw  = (const float*)d_in[6];
    const float* wkv_b = (const float*)d_in[7];
    const float* wo    = (const float*)d_in[8];
    float* out = (float*)d_out;

    float *cq, *c;
    fp16 *xf, *wqaf, *wqbf, *wkvaf, *wkvbf, *wof, *cqf, *kvnf, *af, *qb, *kb, *vb;
    cudaGetSymbolAddress((void**)&cq,   g_cq);
    cudaGetSymbolAddress((void**)&c,    g_c);
    cudaGetSymbolAddress((void**)&xf,   g_xf);
    cudaGetSymbolAddress((void**)&wqaf, g_wqaf);
    cudaGetSymbolAddress((void**)&wqbf, g_wqbf);
    cudaGetSymbolAddress((void**)&wkvaf,g_wkvaf);
    cudaGetSymbolAddress((void**)&wkvbf,g_wkvbf);
    cudaGetSymbolAddress((void**)&wof,  g_wof);
    cudaGetSymbolAddress((void**)&cqf,  g_cqf);
    cudaGetSymbolAddress((void**)&kvnf, g_kvnf);
    cudaGetSymbolAddress((void**)&af,   g_af);
    cudaGetSymbolAddress((void**)&qb,   g_qb);
    cudaGetSymbolAddress((void**)&kb,   g_kb);
    cudaGetSymbolAddress((void**)&vb,   g_vb);

    static cudaStream_t s1 = nullptr, s2 = nullptr;
    static cudaEvent_t eX = nullptr, eWqa = nullptr, eWqb = nullptr, eWkvb = nullptr;
    static cudaEvent_t eWo = nullptr, eKv0 = nullptr, eKv1 = nullptr, eS2 = nullptr;
    if (s1 == nullptr) {
        cudaStreamCreateWithFlags(&s1, cudaStreamNonBlocking);
        cudaStreamCreateWithFlags(&s2, cudaStreamNonBlocking);
        cudaEventCreateWithFlags(&eX,    cudaEventDisableTiming);
        cudaEventCreateWithFlags(&eWqa,  cudaEventDisableTiming);
        cudaEventCreateWithFlags(&eWqb,  cudaEventDisableTiming);
        cudaEventCreateWithFlags(&eWkvb, cudaEventDisableTiming);
        cudaEventCreateWithFlags(&eWo,   cudaEventDisableTiming);
        cudaEventCreateWithFlags(&eKv0,  cudaEventDisableTiming);
        cudaEventCreateWithFlags(&eKv1,  cudaEventDisableTiming);
        cudaEventCreateWithFlags(&eS2,   cudaEventDisableTiming);
    }
    cudaStream_t s0 = 0;

    const int smem128 = STAGES * (16384 + 128*128); // 98304
    const int smem64  = STAGES * (16384 + 64*128);  // 73728
    cudaFuncSetAttribute(gemm_fp16<128,0>, cudaFuncAttributeMaxDynamicSharedMemorySize, smem128);
    cudaFuncSetAttribute(gemm_fp16<128,1>, cudaFuncAttributeMaxDynamicSharedMemorySize, smem128);
    cudaFuncSetAttribute(gemm_fp16<128,2>, cudaFuncAttributeMaxDynamicSharedMemorySize, smem128);
    cudaFuncSetAttribute(gemm_fp16<64,0>,  cudaFuncAttributeMaxDynamicSharedMemorySize, smem64);
    cudaFuncSetAttribute(attn_mma, cudaFuncAttributeMaxDynamicSharedMemorySize, ATT_SMEM_BYTES);

    // NOTE on host issue order: in stream capture every cudaStreamWaitEvent must
    // be issued AFTER its cudaEventRecord (host order). Sections below are
    // topologically sorted accordingly.

    // ---- (1) s0: x, wq_a ----
    cvt_pass_s(x,    xf,   (size_t)ROWS * NDIM, s0);
    cudaEventRecord(eX, s0);
    cvt_pass_s(wq_a, wqaf, (size_t)QRANK * NDIM, s0);
    cudaEventRecord(eWqa, s0);

    // ---- (2) s2 part A: deferred weight cvts ----
    cudaStreamWaitEvent(s2, eX, 0);
    cvt_pass_s(wq_b,  wqbf,  (size_t)QDIM * QRANK, s2);
    cudaEventRecord(eWqb, s2);
    cvt_pass_s(wkv_b, wkvbf, (size_t)KVDIM * KVRANK, s2);
    cudaEventRecord(eWkvb, s2);
    cvt_pass_s(wo,    wof,   (size_t)NDIM * ODIM, s2);
    cudaEventRecord(eWo, s2);

    // ---- (3) s1: kv branch (full GEMM4, per-batch GEMM6) ----
    cudaStreamWaitEvent(s1, eX, 0);
    cvt_pass_s(wkv_a, wkvaf, (size_t)CDIM * NDIM, s1);
    gemm_fp16<64,0><<<dim3(CDIM/64, ROWS/128), 256, smem64, s1>>>(
        xf, wkvaf, c, nullptr, nullptr, nullptr, ROWS, CDIM, NDIM, 0);
    rmsnorm_cvt_k<<<ROWS, 256, 0, s1>>>(c, kvnf, kvnw, KVRANK, CDIM);
    kpe_conv_k<<<(NH*ROWS*32 + 255)/256, 256, 0, s1>>>(c, fc, kb);
    cudaStreamWaitEvent(s1, eWkvb, 0);
    gemm_fp16<128,2><<<dim3(KVDIM/128, SS/128), 256, smem128, s1>>>(
        kvnf, wkvbf, nullptr, kb, vb, nullptr, SS, KVDIM, KVRANK, 0);
    cudaEventRecord(eKv0, s1);
    gemm_fp16<128,2><<<dim3(KVDIM/128, SS/128), 256, smem128, s1>>>(
        kvnf + (size_t)SS * KVRANK, wkvbf, nullptr, kb, vb, nullptr, SS, KVDIM, KVRANK, SS);
    cudaEventRecord(eKv1, s1);

    // ---- (4) s2 part B: full b1 chain ----
    cudaStreamWaitEvent(s2, eWqa, 0);
    gemm_fp16<128,0><<<dim3(QRANK/128, SS/128), 256, smem128, s2>>>(
        xf + (size_t)SS * NDIM, wqaf, cq + (size_t)SS * QRANK,
        nullptr, nullptr, nullptr, SS, QRANK, NDIM, 0);
    rmsnorm_cvt_k<<<SS, 256, 0, s2>>>(cq + (size_t)SS * QRANK, cqf + (size_t)SS * QRANK,
                                      qnw, QRANK, QRANK);
    gemm_fp16<128,1><<<dim3(QDIM/128, SS/128), 256, smem128, s2>>>(
        cqf + (size_t)SS * QRANK, wqbf, nullptr, qb, nullptr, fc, SS, QDIM, QRANK, SS);
    cudaStreamWaitEvent(s2, eKv1, 0);
    attn_mma<<<dim3(SS/64, NH, 1), 128, ATT_SMEM_BYTES, s2>>>(qb, kb, vb, af, 1);
    gemm_fp16<128,0><<<dim3(NDIM/128, SS/128), 256, smem128, s2>>>(
        af + (size_t)SS * ODIM, wof, out + (size_t)SS * NDIM,
        nullptr, nullptr, nullptr, SS, NDIM, ODIM, 0);
    cudaEventRecord(eS2, s2);

    // ---- (5) s0: b0 chain ----
    gemm_fp16<128,0><<<dim3(QRANK/128, SS/128), 256, smem128, s0>>>(
        xf, wqaf, cq, nullptr, nullptr, nullptr, SS, QRANK, NDIM, 0);
    rmsnorm_cvt_k<<<SS, 256, 0, s0>>>(cq, cqf, qnw, QRANK, QRANK);
    cudaStreamWaitEvent(s0, eWqb, 0);
    gemm_fp16<128,1><<<dim3(QDIM/128, SS/128), 256, smem128, s0>>>(
        cqf, wqbf, nullptr, qb, nullptr, fc, SS, QDIM, QRANK, 0);
    cudaStreamWaitEvent(s0, eKv0, 0);
    attn_mma<<<dim3(SS/64, NH, 1), 128, ATT_SMEM_BYTES, s0>>>(qb, kb, vb, af, 0);
    cudaStreamWaitEvent(s0, eWo, 0);
    gemm_fp16<128,0><<<dim3(NDIM/128, SS/128), 256, smem128, s0>>>(
        af, wof, out, nullptr, nullptr, nullptr, SS, NDIM, ODIM, 0);

    // join s2 back into the capture-origin stream
    cudaStreamWaitEvent(s0, eS2, 0);
}